// round 1
// baseline (speedup 1.0000x reference)
#include <cuda_runtime.h>

#define NN 100000
#define CH 128
#define BM 64
#define SW_STRIDE 129
#define SA_STRIDE 132
#define SMEM_BYTES ((2*128*SW_STRIDE + 2*BM*SA_STRIDE) * 4)

__device__ __align__(128) float g_agg[(size_t)NN * CH];
__device__ __align__(128) float g_h[(size_t)NN * CH];
__device__ float g_cnt[NN];
__device__ int g_is64;

// Detect whether edge_index is int64 (high words all zero) or int32.
__global__ void detect_kernel(const int* __restrict__ ei, int E) {
    __shared__ int s_any;
    if (threadIdx.x == 0) s_any = 0;
    __syncthreads();
    int nchk = E < 1024 ? E : 1024;
    int acc = 0;
    for (int e = threadIdx.x; e < nchk; e += blockDim.x)
        acc |= ei[2 * e + 1];
    if (acc) atomicOr(&s_any, 1);
    __syncthreads();
    if (threadIdx.x == 0) g_is64 = (s_any ? 0 : 1);
}

__global__ void zero_kernel(int zero_cnt_flag) {
    size_t stride = (size_t)gridDim.x * blockDim.x;
    size_t i0 = (size_t)blockIdx.x * blockDim.x + threadIdx.x;
    float4 z = make_float4(0.f, 0.f, 0.f, 0.f);
    size_t total4 = (size_t)NN * CH / 4;
    float4* agg4 = (float4*)g_agg;
    for (size_t i = i0; i < total4; i += stride) agg4[i] = z;
    if (zero_cnt_flag) {
        for (size_t i = i0; i < NN; i += stride) g_cnt[i] = 0.f;
    }
}

__global__ void degree_kernel(const int* __restrict__ ei, int E) {
    int e = blockIdx.x * blockDim.x + threadIdx.x;
    if (e >= E) return;
    int is64 = g_is64;
    int dst = is64 ? ei[2 * (E + e)] : ei[E + e];
    atomicAdd(&g_cnt[dst], 1.0f);
}

// One warp per edge: gather 512B row of feat[src], vec4-reduce into g_agg[dst].
__global__ void scatter_kernel(const float* __restrict__ feat,
                               const int* __restrict__ ei, int E) {
    int gid = blockIdx.x * blockDim.x + threadIdx.x;
    int e = gid >> 5;
    int lane = gid & 31;
    if (e >= E) return;
    int is64 = g_is64;
    int src, dst;
    if (is64) {
        src = ei[2 * e];
        dst = ei[2 * (E + e)];
    } else {
        src = ei[e];
        dst = ei[E + e];
    }
    float4 v = ((const float4*)(feat + (size_t)src * CH))[lane];
    float* dp = g_agg + (size_t)dst * CH + lane * 4;
    asm volatile("red.global.add.v4.f32 [%0], {%1,%2,%3,%4};"
                 :: "l"(dp), "f"(v.x), "f"(v.y), "f"(v.z), "f"(v.w)
                 : "memory");
}

// Fused SAGE layer: out = act( (g_agg/max(cnt,1)) @ Wl^T + bl + A2 @ Wr^T )
// Block: 64 rows x 128 cols, 256 threads, each thread 4 rows x 8 cols.
__global__ void __launch_bounds__(256, 1)
layer_kernel(const float* __restrict__ A2,
             const float* __restrict__ Wl,
             const float* __restrict__ Wr,
             const float* __restrict__ bl,
             float* __restrict__ out,
             int n, int apply_sig) {
    extern __shared__ float sm[];
    float* sWl = sm;                          // [128][129]
    float* sWr = sWl + 128 * SW_STRIDE;       // [128][129]
    float* sAl = sWr + 128 * SW_STRIDE;       // [64][132]  agg, pre-scaled by 1/cnt
    float* sAr = sAl + BM * SA_STRIDE;        // [64][132]  A2

    int tid = threadIdx.x;
    int row0 = blockIdx.x * BM;

    // Load weights (natural [j][k] layout, padded stride -> conflict-free).
    for (int idx = tid; idx < 128 * 128; idx += 256) {
        int j = idx >> 7, k = idx & 127;
        sWl[j * SW_STRIDE + k] = Wl[idx];
        sWr[j * SW_STRIDE + k] = Wr[idx];
    }

    // Load A tiles (row-major, float4-aligned padded stride).
    for (int idx = tid; idx < BM * 32; idx += 256) {
        int r = idx >> 5, k4 = idx & 31;
        int row = row0 + r;
        float4 va = make_float4(0.f, 0.f, 0.f, 0.f);
        float4 vx = va;
        if (row < n) {
            float s = 1.0f / fmaxf(g_cnt[row], 1.0f);
            va = ((const float4*)(g_agg + (size_t)row * CH))[k4];
            va.x *= s; va.y *= s; va.z *= s; va.w *= s;
            vx = ((const float4*)(A2 + (size_t)row * CH))[k4];
        }
        ((float4*)(sAl + r * SA_STRIDE))[k4] = va;
        ((float4*)(sAr + r * SA_STRIDE))[k4] = vx;
    }
    __syncthreads();

    int tx = tid & 15;     // col group: cols tx + 16*j
    int ty = tid >> 4;     // row group: rows ty*4 .. ty*4+3

    float acc[4][8];
#pragma unroll
    for (int i = 0; i < 4; ++i)
#pragma unroll
        for (int j = 0; j < 8; ++j) acc[i][j] = 0.f;

    const float* As = sAl;
    const float* Ws = sWl;
#pragma unroll 1
    for (int part = 0; part < 2; ++part) {
        const float* a_base = As + (ty * 4) * SA_STRIDE;
        const float* w_base = Ws + tx * SW_STRIDE;
#pragma unroll 4
        for (int k = 0; k < 128; ++k) {
            float a0 = a_base[0 * SA_STRIDE + k];
            float a1 = a_base[1 * SA_STRIDE + k];
            float a2 = a_base[2 * SA_STRIDE + k];
            float a3 = a_base[3 * SA_STRIDE + k];
#pragma unroll
            for (int j = 0; j < 8; ++j) {
                float w = w_base[(16 * j) * SW_STRIDE + k];
                acc[0][j] += a0 * w;
                acc[1][j] += a1 * w;
                acc[2][j] += a2 * w;
                acc[3][j] += a3 * w;
            }
        }
        As = sAr;
        Ws = sWr;
    }

#pragma unroll
    for (int j = 0; j < 8; ++j) {
        int col = tx + 16 * j;
        float b = __ldg(&bl[col]);
#pragma unroll
        for (int i = 0; i < 4; ++i) {
            int row = row0 + ty * 4 + i;
            if (row < n) {
                float v = acc[i][j] + b;
                if (apply_sig) v = 1.0f / (1.0f + __expf(-v));
                out[(size_t)row * CH + col] = v;
            }
        }
    }
}

extern "C" void kernel_launch(void* const* d_in, const int* in_sizes, int n_in,
                              void* d_out, int out_size) {
    const float* x   = (const float*)d_in[0];
    const int*   ei  = (const int*)d_in[1];
    const float* W1l = (const float*)d_in[2];
    const float* b1l = (const float*)d_in[3];
    const float* W1r = (const float*)d_in[4];
    const float* W2l = (const float*)d_in[5];
    const float* b2l = (const float*)d_in[6];
    const float* W2r = (const float*)d_in[7];
    float* out = (float*)d_out;

    int n = in_sizes[0] / CH;   // 100000
    int E = in_sizes[1] / 2;    // 625000 (element count / 2 regardless of dtype)

    float* h_ptr = nullptr;
    cudaGetSymbolAddress((void**)&h_ptr, g_h);

    cudaFuncSetAttribute(layer_kernel,
                         cudaFuncAttributeMaxDynamicSharedMemorySize, SMEM_BYTES);

    int grid_layer = (n + BM - 1) / BM;
    int grid_edge_t = (E + 255) / 256;
    long long scat_threads = (long long)E * 32;
    int grid_scat = (int)((scat_threads + 255) / 256);

    detect_kernel<<<1, 256>>>(ei, E);
    zero_kernel<<<2048, 256>>>(1);
    degree_kernel<<<grid_edge_t, 256>>>(ei, E);

    // Layer 1
    scatter_kernel<<<grid_scat, 256>>>(x, ei, E);
    layer_kernel<<<grid_layer, 256, SMEM_BYTES>>>(x, W1l, W1r, b1l, h_ptr, n, 1);

    // Layer 2
    zero_kernel<<<2048, 256>>>(0);
    scatter_kernel<<<grid_scat, 256>>>(h_ptr, ei, E);
    layer_kernel<<<grid_layer, 256, SMEM_BYTES>>>(h_ptr, W2l, W2r, b2l, out, n, 0);
}

// round 2
// speedup vs baseline: 1.1281x; 1.1281x over previous
#include <cuda_runtime.h>

#define NN 100000
#define CH 128
#define BM 128
#define WSTR 130
#define ASTR 132
#define SMEM_WORDS (2 * 128 * WSTR + BM * ASTR)
#define SMEM_BYTES (SMEM_WORDS * 4)

typedef unsigned long long ull;

__device__ __align__(128) float g_agg[(size_t)NN * CH];
__device__ __align__(128) float g_h[(size_t)NN * CH];
__device__ float g_cnt[NN];
__device__ int g_is64;

// Detect whether edge_index is int64 (high words all zero) or int32.
__global__ void detect_kernel(const int* __restrict__ ei, int E) {
    __shared__ int s_any;
    if (threadIdx.x == 0) s_any = 0;
    __syncthreads();
    int nchk = E < 1024 ? E : 1024;
    int acc = 0;
    for (int e = threadIdx.x; e < nchk; e += blockDim.x)
        acc |= ei[2 * e + 1];
    if (acc) atomicOr(&s_any, 1);
    __syncthreads();
    if (threadIdx.x == 0) g_is64 = (s_any ? 0 : 1);
}

__global__ void zero_kernel(int zero_cnt_flag) {
    size_t stride = (size_t)gridDim.x * blockDim.x;
    size_t i0 = (size_t)blockIdx.x * blockDim.x + threadIdx.x;
    float4 z = make_float4(0.f, 0.f, 0.f, 0.f);
    size_t total4 = (size_t)NN * CH / 4;
    float4* agg4 = (float4*)g_agg;
    for (size_t i = i0; i < total4; i += stride) agg4[i] = z;
    if (zero_cnt_flag) {
        for (size_t i = i0; i < NN; i += stride) g_cnt[i] = 0.f;
    }
}

__global__ void degree_kernel(const int* __restrict__ ei, int E) {
    int e = blockIdx.x * blockDim.x + threadIdx.x;
    if (e >= E) return;
    int is64 = g_is64;
    int dst = is64 ? ei[2 * (E + e)] : ei[E + e];
    atomicAdd(&g_cnt[dst], 1.0f);
}

// One warp per edge: gather 512B row of feat[src], vec4-reduce into g_agg[dst].
__global__ void scatter_kernel(const float* __restrict__ feat,
                               const int* __restrict__ ei, int E) {
    int gid = blockIdx.x * blockDim.x + threadIdx.x;
    int e = gid >> 5;
    int lane = gid & 31;
    if (e >= E) return;
    int is64 = g_is64;
    int src, dst;
    if (is64) {
        src = ei[2 * e];
        dst = ei[2 * (E + e)];
    } else {
        src = ei[e];
        dst = ei[E + e];
    }
    float4 v = ((const float4*)(feat + (size_t)src * CH))[lane];
    float* dp = g_agg + (size_t)dst * CH + lane * 4;
    asm volatile("red.global.add.v4.f32 [%0], {%1,%2,%3,%4};"
                 :: "l"(dp), "f"(v.x), "f"(v.y), "f"(v.z), "f"(v.w)
                 : "memory");
}

__device__ __forceinline__ ull splat2(float a) {
    ull r;
    asm("mov.b64 %0, {%1, %1};" : "=l"(r) : "f"(a));
    return r;
}
__device__ __forceinline__ void fma2(ull& d, ull a, ull b) {
    asm("fma.rn.f32x2 %0, %1, %2, %0;" : "+l"(d) : "l"(a), "l"(b));
}
__device__ __forceinline__ float2 unpack2(ull v) {
    float2 r;
    asm("mov.b64 {%0, %1}, %2;" : "=f"(r.x), "=f"(r.y) : "l"(v));
    return r;
}

// Persistent fused SAGE layer:
//   out = act( (g_agg/max(cnt,1)) @ Wl^T + bl + A2 @ Wr^T )
// Both W's cached k-major in smem for the whole kernel; per tile two K-passes
// over a shared A buffer. 256 threads, 128x128 block tile, 8x8 thread tile,
// FFMA2 (fma.rn.f32x2) packed over column pairs.
__global__ void __launch_bounds__(256, 1)
layer_kernel(const float* __restrict__ A2,
             const float* __restrict__ Wl,
             const float* __restrict__ Wr,
             const float* __restrict__ bl,
             float* __restrict__ out,
             int n, int apply_sig, int ntiles) {
    extern __shared__ float sm[];
    float* sWl = sm;                   // [k][c], stride WSTR (k-major)
    float* sWr = sWl + 128 * WSTR;
    float* sA  = sWr + 128 * WSTR;     // [r][k], stride ASTR

    int tid = threadIdx.x;

    // Load both weights transposed to k-major once per block.
    for (int idx = tid; idx < CH * CH; idx += 256) {
        int c = idx >> 7, k = idx & 127;
        sWl[k * WSTR + c] = Wl[idx];
        sWr[k * WSTR + c] = Wr[idx];
    }

    int tx = tid & 15;   // column-pair group: pairs p = tx + 16*jp -> cols 2p, 2p+1
    int ty = tid >> 4;   // row group: rows ty*8 .. ty*8+7

    float2 bv[4];
#pragma unroll
    for (int jp = 0; jp < 4; ++jp)
        bv[jp] = *(const float2*)(bl + 2 * (tx + 16 * jp));

    for (int tile = blockIdx.x; tile < ntiles; tile += gridDim.x) {
        int row0 = tile * BM;

        ull acc[8][4];
#pragma unroll
        for (int i = 0; i < 8; ++i)
#pragma unroll
            for (int jp = 0; jp < 4; ++jp) acc[i][jp] = 0ull;

#pragma unroll 1
        for (int part = 0; part < 2; ++part) {
            __syncthreads();   // previous pass / previous tile done with sA
            // Load A tile (part 0: scaled agg; part 1: root features).
            for (int idx = tid; idx < BM * 32; idx += 256) {
                int r = idx >> 5, k4 = idx & 31;
                int row = row0 + r;
                float4 v = make_float4(0.f, 0.f, 0.f, 0.f);
                if (row < n) {
                    if (part == 0) {
                        float s = 1.0f / fmaxf(g_cnt[row], 1.0f);
                        v = ((const float4*)(g_agg + (size_t)row * CH))[k4];
                        v.x *= s; v.y *= s; v.z *= s; v.w *= s;
                    } else {
                        v = ((const float4*)(A2 + (size_t)row * CH))[k4];
                    }
                }
                ((float4*)(sA + r * ASTR))[k4] = v;
            }
            __syncthreads();

            const float* wtx = (part ? sWr : sWl) + 2 * tx;
            const float* abase = sA + (ty * 8) * ASTR;

#pragma unroll 2
            for (int k = 0; k < CH; ++k) {
                ull wp[4];
#pragma unroll
                for (int jp = 0; jp < 4; ++jp)
                    wp[jp] = *(const ull*)(wtx + k * WSTR + 32 * jp);
                ull as[8];
#pragma unroll
                for (int i = 0; i < 8; ++i)
                    as[i] = splat2(abase[i * ASTR + k]);
#pragma unroll
                for (int i = 0; i < 8; ++i)
#pragma unroll
                    for (int jp = 0; jp < 4; ++jp)
                        fma2(acc[i][jp], as[i], wp[jp]);
            }
        }

        // Epilogue: bias + optional sigmoid, float2 stores.
#pragma unroll
        for (int i = 0; i < 8; ++i) {
            int row = row0 + ty * 8 + i;
            if (row < n) {
#pragma unroll
                for (int jp = 0; jp < 4; ++jp) {
                    float2 v = unpack2(acc[i][jp]);
                    v.x += bv[jp].x;
                    v.y += bv[jp].y;
                    if (apply_sig) {
                        v.x = 1.0f / (1.0f + __expf(-v.x));
                        v.y = 1.0f / (1.0f + __expf(-v.y));
                    }
                    *(float2*)(out + (size_t)row * CH + 2 * (tx + 16 * jp)) = v;
                }
            }
        }
    }
}

extern "C" void kernel_launch(void* const* d_in, const int* in_sizes, int n_in,
                              void* d_out, int out_size) {
    const float* x   = (const float*)d_in[0];
    const int*   ei  = (const int*)d_in[1];
    const float* W1l = (const float*)d_in[2];
    const float* b1l = (const float*)d_in[3];
    const float* W1r = (const float*)d_in[4];
    const float* W2l = (const float*)d_in[5];
    const float* b2l = (const float*)d_in[6];
    const float* W2r = (const float*)d_in[7];
    float* out = (float*)d_out;

    int n = in_sizes[0] / CH;   // 100000
    int E = in_sizes[1] / 2;    // 625000

    float* h_ptr = nullptr;
    cudaGetSymbolAddress((void**)&h_ptr, g_h);

    cudaFuncSetAttribute(layer_kernel,
                         cudaFuncAttributeMaxDynamicSharedMemorySize, SMEM_BYTES);

    int ntiles = (n + BM - 1) / BM;
    int grid_layer = ntiles < 148 ? ntiles : 148;
    int grid_edge_t = (E + 255) / 256;
    long long scat_threads = (long long)E * 32;
    int grid_scat = (int)((scat_threads + 255) / 256);

    detect_kernel<<<1, 256>>>(ei, E);
    zero_kernel<<<2048, 256>>>(1);
    degree_kernel<<<grid_edge_t, 256>>>(ei, E);

    // Layer 1
    scatter_kernel<<<grid_scat, 256>>>(x, ei, E);
    layer_kernel<<<grid_layer, 256, SMEM_BYTES>>>(x, W1l, W1r, b1l, h_ptr, n, 1, ntiles);

    // Layer 2
    zero_kernel<<<2048, 256>>>(0);
    scatter_kernel<<<grid_scat, 256>>>(h_ptr, ei, E);
    layer_kernel<<<grid_layer, 256, SMEM_BYTES>>>(h_ptr, W2l, W2r, b2l, out, n, 0, ntiles);
}

// round 4
// speedup vs baseline: 1.6167x; 1.4331x over previous
#include <cuda_runtime.h>
#include <cuda_bf16.h>

#define NN 100000
#define CH 128
#define BM 128

typedef unsigned long long ull;
typedef unsigned int u32;

// ---- smem byte offsets (layer kernel) ----
#define OFF_BIAS 0
#define OFF_WLH 512
#define OFF_WLL (OFF_WLH + 32768)
#define OFF_WRH (OFF_WLL + 32768)
#define OFF_WRL (OFF_WRH + 32768)
#define OFF_AH  (OFF_WRL + 32768)
#define OFF_AL  (OFF_AH + 32768)
#define SMEM_TOTAL (OFF_AL + 32768)   // 197120 bytes

__device__ __align__(128) float g_agg[(size_t)NN * CH];
__device__ __align__(128) float g_h[(size_t)NN * CH];
__device__ float g_cnt[NN];
__device__ int g_is64;

// ---------------- helpers ----------------
__device__ __forceinline__ u32 smem_u32(const void* p) {
    u32 a;
    asm("{ .reg .u64 t; cvta.to.shared.u64 t, %1; cvt.u32.u64 %0, t; }"
        : "=r"(a) : "l"(p));
    return a;
}
__device__ __forceinline__ void ldsm4(u32* r, u32 addr) {
    asm volatile("ldmatrix.sync.aligned.m8n8.x4.shared.b16 {%0,%1,%2,%3}, [%4];"
                 : "=r"(r[0]), "=r"(r[1]), "=r"(r[2]), "=r"(r[3]) : "r"(addr));
}
__device__ __forceinline__ void mma16816(float* d, const u32* a, const u32* b) {
    asm volatile(
        "mma.sync.aligned.m16n8k16.row.col.f32.bf16.bf16.f32 "
        "{%0,%1,%2,%3}, {%4,%5,%6,%7}, {%8,%9}, {%0,%1,%2,%3};"
        : "+f"(d[0]), "+f"(d[1]), "+f"(d[2]), "+f"(d[3])
        : "r"(a[0]), "r"(a[1]), "r"(a[2]), "r"(a[3]), "r"(b[0]), "r"(b[1]));
}
__device__ __forceinline__ ull pack4bf(__nv_bfloat16 a, __nv_bfloat16 b,
                                       __nv_bfloat16 c, __nv_bfloat16 d) {
    u32 lo = ((u32)__bfloat16_as_ushort(b) << 16) | __bfloat16_as_ushort(a);
    u32 hi = ((u32)__bfloat16_as_ushort(d) << 16) | __bfloat16_as_ushort(c);
    return ((ull)hi << 32) | lo;
}
// byte offset of 4 bf16 at (row r, float4-col q) in a swizzled [128][128] bf16 tile:
// 256B rows; 16B chunks XOR-swizzled with (r & 7).
__device__ __forceinline__ u32 swz_off(int r, int q) {
    return ((u32)r << 8) + ((u32)(((q >> 1) ^ (r & 7))) << 4) + ((u32)(q & 1) << 3);
}

// ---------------- aggregation kernels ----------------
__global__ void detect_kernel(const int* __restrict__ ei, int E) {
    __shared__ int s_any;
    if (threadIdx.x == 0) s_any = 0;
    __syncthreads();
    int nchk = E < 1024 ? E : 1024;
    int acc = 0;
    for (int e = threadIdx.x; e < nchk; e += blockDim.x)
        acc |= ei[2 * e + 1];
    if (acc) atomicOr(&s_any, 1);
    __syncthreads();
    if (threadIdx.x == 0) g_is64 = (s_any ? 0 : 1);
}

__global__ void zero_kernel(int zero_cnt_flag) {
    size_t stride = (size_t)gridDim.x * blockDim.x;
    size_t i0 = (size_t)blockIdx.x * blockDim.x + threadIdx.x;
    float4 z = make_float4(0.f, 0.f, 0.f, 0.f);
    size_t total4 = (size_t)NN * CH / 4;
    float4* agg4 = (float4*)g_agg;
    for (size_t i = i0; i < total4; i += stride) agg4[i] = z;
    if (zero_cnt_flag) {
        for (size_t i = i0; i < NN; i += stride) g_cnt[i] = 0.f;
    }
}

__global__ void degree_kernel(const int* __restrict__ ei, int E) {
    int e = blockIdx.x * blockDim.x + threadIdx.x;
    if (e >= E) return;
    int is64 = g_is64;
    int dst = is64 ? ei[2 * (E + e)] : ei[E + e];
    atomicAdd(&g_cnt[dst], 1.0f);
}

__global__ void scatter_kernel(const float* __restrict__ feat,
                               const int* __restrict__ ei, int E) {
    int gid = blockIdx.x * blockDim.x + threadIdx.x;
    int e = gid >> 5;
    int lane = gid & 31;
    if (e >= E) return;
    int is64 = g_is64;
    int src, dst;
    if (is64) {
        src = ei[2 * e];
        dst = ei[2 * (E + e)];
    } else {
        src = ei[e];
        dst = ei[E + e];
    }
    float4 v = ((const float4*)(feat + (size_t)src * CH))[lane];
    float* dp = g_agg + (size_t)dst * CH + lane * 4;
    asm volatile("red.global.add.v4.f32 [%0], {%1,%2,%3,%4};"
                 :: "l"(dp), "f"(v.x), "f"(v.y), "f"(v.z), "f"(v.w)
                 : "memory");
}

// ---------------- HMMA fused SAGE layer ----------------
// out = act( (g_agg/max(cnt,1)) @ Wl^T + bl + A2 @ Wr^T )
// Split-bf16 3-term: v = hi + lo; GEMM = Ah*Wh + Ah*Wl + Al*Wh (fp32 accum).

__device__ __forceinline__ void split_store(char* hi, char* lo, int r, int q, float4 v) {
    __nv_bfloat16 hx = __float2bfloat16_rn(v.x);
    __nv_bfloat16 hy = __float2bfloat16_rn(v.y);
    __nv_bfloat16 hz = __float2bfloat16_rn(v.z);
    __nv_bfloat16 hw = __float2bfloat16_rn(v.w);
    u32 off = swz_off(r, q);
    *(ull*)(hi + off) = pack4bf(hx, hy, hz, hw);
    *(ull*)(lo + off) = pack4bf(
        __float2bfloat16_rn(v.x - __bfloat162float(hx)),
        __float2bfloat16_rn(v.y - __bfloat162float(hy)),
        __float2bfloat16_rn(v.z - __bfloat162float(hz)),
        __float2bfloat16_rn(v.w - __bfloat162float(hw)));
}

__device__ __forceinline__ void load_convert_A(const float* __restrict__ src,
                                               char* ah, char* al,
                                               int row0, int n, int do_scale, int tid) {
    for (int idx = tid; idx < BM * 32; idx += 256) {
        int r = idx >> 5, q = idx & 31;
        int row = row0 + r;
        float4 v = make_float4(0.f, 0.f, 0.f, 0.f);
        if (row < n) {
            v = ((const float4*)(src + (size_t)row * CH))[q];
            if (do_scale) {
                float s = 1.0f / fmaxf(g_cnt[row], 1.0f);
                v.x *= s; v.y *= s; v.z *= s; v.w *= s;
            }
        }
        split_store(ah, al, r, q, v);
    }
}

// One GEMM half: acc += split(A) @ split(W)^T over K=128.
__device__ __forceinline__ void mma_pass(u32 abh, u32 abl, u32 wbh, u32 wbl,
                                         float acc[2][8][4],
                                         const u32* rowA256, u32 rowA7, u32 kbitA,
                                         const u32* rw256, const u32* rw7, u32 kgrpW) {
#pragma unroll
    for (int ks = 0; ks < 8; ++ks) {
        u32 ks2 = (u32)(ks << 1);
        u32 ah[2][4], al[2][4], wh[4][4], wl[4][4];
        u32 ca = ((ks2 | kbitA) ^ rowA7) << 4;
#pragma unroll
        for (int mt = 0; mt < 2; ++mt) {
            ldsm4(ah[mt], abh + rowA256[mt] + ca);
            ldsm4(al[mt], abl + rowA256[mt] + ca);
        }
#pragma unroll
        for (int nt2 = 0; nt2 < 4; ++nt2) {
            u32 cw = ((ks2 | kgrpW) ^ rw7[nt2]) << 4;
            ldsm4(wh[nt2], wbh + rw256[nt2] + cw);
            ldsm4(wl[nt2], wbl + rw256[nt2] + cw);
        }
#pragma unroll
        for (int mt = 0; mt < 2; ++mt) {
#pragma unroll
            for (int nt = 0; nt < 8; ++nt) {
                const u32* bh = &wh[nt >> 1][(nt & 1) * 2];
                const u32* bl2 = &wl[nt >> 1][(nt & 1) * 2];
                mma16816(acc[mt][nt], ah[mt], bh);
                mma16816(acc[mt][nt], ah[mt], bl2);
                mma16816(acc[mt][nt], al[mt], bh);
            }
        }
    }
}

__global__ void __launch_bounds__(256, 1)
layer_kernel(const float* __restrict__ A2,
             const float* __restrict__ Wl,
             const float* __restrict__ Wr,
             const float* __restrict__ bl,
             float* __restrict__ out,
             int n, int apply_sig, int ntiles) {
    extern __shared__ char sm[];
    u32 smb = smem_u32(sm);
    float* sBias = (float*)(sm + OFF_BIAS);
    int tid = threadIdx.x, wid = tid >> 5, lane = tid & 31;
    int warp_m = wid & 3, warp_n = wid >> 2;

    // Prologue: split both weight matrices (stored [n][k]) into bf16 hi/lo.
    for (int idx = tid; idx < 128 * 32; idx += 256) {
        int r = idx >> 5, q = idx & 31;
        split_store(sm + OFF_WLH, sm + OFF_WLL, r, q, ((const float4*)Wl)[idx]);
        split_store(sm + OFF_WRH, sm + OFF_WRL, r, q, ((const float4*)Wr)[idx]);
    }
    if (tid < 128) sBias[tid] = bl[tid];

    // Per-lane ldmatrix address precomputation.
    u32 rowA256[2], rowA7;
    {
        int ra0 = warp_m * 32 + (lane & 15);
        rowA256[0] = (u32)(ra0 << 8);
        rowA256[1] = (u32)((ra0 + 16) << 8);
        rowA7 = (u32)(ra0 & 7);
    }
    u32 kbitA = (u32)(lane >> 4);
    u32 rw256[4], rw7[4];
    u32 kgrpW = (u32)((lane >> 3) & 1);
    {
        int base = warp_n * 64 + (lane & 7) + ((lane >> 4) << 3);
#pragma unroll
        for (int nt2 = 0; nt2 < 4; ++nt2) {
            int rw = base + nt2 * 16;
            rw256[nt2] = (u32)(rw << 8);
            rw7[nt2] = (u32)(rw & 7);
        }
    }

    int g = lane >> 2, c2 = (lane & 3) * 2;

    for (int tile = blockIdx.x; tile < ntiles; tile += gridDim.x) {
        int row0 = tile * BM;

        float acc[2][8][4];
#pragma unroll
        for (int mt = 0; mt < 2; ++mt)
#pragma unroll
            for (int nt = 0; nt < 8; ++nt)
#pragma unroll
                for (int i = 0; i < 4; ++i) acc[mt][nt][i] = 0.f;

        // pass 0: scaled aggregated neighbors @ Wl
        __syncthreads();   // prior tile done reading A buffers
        load_convert_A(g_agg, sm + OFF_AH, sm + OFF_AL, row0, n, 1, tid);
        __syncthreads();
        mma_pass(smb + OFF_AH, smb + OFF_AL, smb + OFF_WLH, smb + OFF_WLL,
                 acc, rowA256, rowA7, kbitA, rw256, rw7, kgrpW);

        // pass 1: root features @ Wr
        __syncthreads();
        load_convert_A(A2, sm + OFF_AH, sm + OFF_AL, row0, n, 0, tid);
        __syncthreads();
        mma_pass(smb + OFF_AH, smb + OFF_AL, smb + OFF_WRH, smb + OFF_WRL,
                 acc, rowA256, rowA7, kbitA, rw256, rw7, kgrpW);

        // epilogue: bias + optional sigmoid, float2 stores
#pragma unroll
        for (int mt = 0; mt < 2; ++mt) {
#pragma unroll
            for (int half = 0; half < 2; ++half) {
                int row = row0 + warp_m * 32 + mt * 16 + g + half * 8;
                if (row < n) {
                    float* op = out + (size_t)row * CH + warp_n * 64 + c2;
#pragma unroll
                    for (int nt = 0; nt < 8; ++nt) {
                        int col = warp_n * 64 + nt * 8 + c2;
                        float2 v;
                        v.x = acc[mt][nt][half * 2 + 0] + sBias[col];
                        v.y = acc[mt][nt][half * 2 + 1] + sBias[col + 1];
                        if (apply_sig) {
                            v.x = 1.0f / (1.0f + __expf(-v.x));
                            v.y = 1.0f / (1.0f + __expf(-v.y));
                        }
                        *(float2*)(op + nt * 8) = v;
                    }
                }
            }
        }
    }
}

extern "C" void kernel_launch(void* const* d_in, const int* in_sizes, int n_in,
                              void* d_out, int out_size) {
    const float* x   = (const float*)d_in[0];
    const int*   ei  = (const int*)d_in[1];
    const float* W1l = (const float*)d_in[2];
    const float* b1l = (const float*)d_in[3];
    const float* W1r = (const float*)d_in[4];
    const float* W2l = (const float*)d_in[5];
    const float* b2l = (const float*)d_in[6];
    const float* W2r = (const float*)d_in[7];
    float* out = (float*)d_out;

    int n = in_sizes[0] / CH;   // 100000
    int E = in_sizes[1] / 2;    // 625000

    float* h_ptr = nullptr;
    cudaGetSymbolAddress((void**)&h_ptr, g_h);

    cudaFuncSetAttribute(layer_kernel,
                         cudaFuncAttributeMaxDynamicSharedMemorySize, SMEM_TOTAL);

    int ntiles = (n + BM - 1) / BM;
    int grid_layer = ntiles < 148 ? ntiles : 148;
    int grid_edge_t = (E + 255) / 256;
    long long scat_threads = (long long)E * 32;
    int grid_scat = (int)((scat_threads + 255) / 256);

    detect_kernel<<<1, 256>>>(ei, E);
    zero_kernel<<<2048, 256>>>(1);
    degree_kernel<<<grid_edge_t, 256>>>(ei, E);

    // Layer 1
    scatter_kernel<<<grid_scat, 256>>>(x, ei, E);
    layer_kernel<<<grid_layer, 256, SMEM_TOTAL>>>(x, W1l, W1r, b1l, h_ptr, n, 1, ntiles);

    // Layer 2
    zero_kernel<<<2048, 256>>>(0);
    scatter_kernel<<<grid_scat, 256>>>(h_ptr, ei, E);
    layer_kernel<<<grid_layer, 256, SMEM_TOTAL>>>(h_ptr, W2l, W2r, b2l, out, n, 0, ntiles);
}

// round 5
// speedup vs baseline: 2.6914x; 1.6648x over previous
#include <cuda_runtime.h>
#include <cuda_bf16.h>

#define NN 100000
#define EMAX 700000
#define CH 128
#define BM 64

typedef unsigned long long ull;
typedef unsigned int u32;

// ---- smem byte offsets (layer kernel) ----
#define OFF_BIAS 0
#define OFF_WLH 512
#define OFF_WLL (OFF_WLH + 32768)
#define OFF_WRH (OFF_WLL + 32768)
#define OFF_WRL (OFF_WRH + 32768)
#define OFF_AGH (OFF_WRL + 32768)
#define OFF_AGL (OFF_AGH + 16384)
#define OFF_AXH (OFF_AGL + 16384)
#define OFF_AXL (OFF_AXH + 16384)
#define SMEM_TOTAL (OFF_AXL + 16384)   // 197120 bytes

__device__ __align__(128) float g_agg[(size_t)NN * CH];
__device__ __align__(128) float g_h[(size_t)NN * CH];
__device__ int g_deg[NN];
__device__ int g_off[NN + 1];
__device__ int g_cursor[NN];
__device__ int g_bsum[128];
__device__ int g_boff[128];
__device__ int g_ssrc[EMAX];
__device__ int g_is64;

// ---------------- helpers ----------------
__device__ __forceinline__ u32 smem_u32(const void* p) {
    u32 a;
    asm("{ .reg .u64 t; cvta.to.shared.u64 t, %1; cvt.u32.u64 %0, t; }"
        : "=r"(a) : "l"(p));
    return a;
}
__device__ __forceinline__ void ldsm4(u32* r, u32 addr) {
    asm volatile("ldmatrix.sync.aligned.m8n8.x4.shared.b16 {%0,%1,%2,%3}, [%4];"
                 : "=r"(r[0]), "=r"(r[1]), "=r"(r[2]), "=r"(r[3]) : "r"(addr));
}
__device__ __forceinline__ void mma16816(float* d, const u32* a, const u32* b) {
    asm volatile(
        "mma.sync.aligned.m16n8k16.row.col.f32.bf16.bf16.f32 "
        "{%0,%1,%2,%3}, {%4,%5,%6,%7}, {%8,%9}, {%0,%1,%2,%3};"
        : "+f"(d[0]), "+f"(d[1]), "+f"(d[2]), "+f"(d[3])
        : "r"(a[0]), "r"(a[1]), "r"(a[2]), "r"(a[3]), "r"(b[0]), "r"(b[1]));
}
__device__ __forceinline__ ull pack4bf(__nv_bfloat16 a, __nv_bfloat16 b,
                                       __nv_bfloat16 c, __nv_bfloat16 d) {
    u32 lo = ((u32)__bfloat16_as_ushort(b) << 16) | __bfloat16_as_ushort(a);
    u32 hi = ((u32)__bfloat16_as_ushort(d) << 16) | __bfloat16_as_ushort(c);
    return ((ull)hi << 32) | lo;
}
// byte offset of 4 bf16 at (row r, float4-col q); 256B rows, 16B-chunk XOR swizzle.
__device__ __forceinline__ u32 swz_off(int r, int q) {
    return ((u32)r << 8) + ((u32)(((q >> 1) ^ (r & 7))) << 4) + ((u32)(q & 1) << 3);
}
__device__ __forceinline__ void split_store(char* hi, char* lo, int r, int q, float4 v) {
    __nv_bfloat16 hx = __float2bfloat16_rn(v.x);
    __nv_bfloat16 hy = __float2bfloat16_rn(v.y);
    __nv_bfloat16 hz = __float2bfloat16_rn(v.z);
    __nv_bfloat16 hw = __float2bfloat16_rn(v.w);
    u32 off = swz_off(r, q);
    *(ull*)(hi + off) = pack4bf(hx, hy, hz, hw);
    *(ull*)(lo + off) = pack4bf(
        __float2bfloat16_rn(v.x - __bfloat162float(hx)),
        __float2bfloat16_rn(v.y - __bfloat162float(hy)),
        __float2bfloat16_rn(v.z - __bfloat162float(hz)),
        __float2bfloat16_rn(v.w - __bfloat162float(hw)));
}

// ---------------- graph preprocessing (CSR by dst, run once per replay) ----------------
__global__ void detect_kernel(const int* __restrict__ ei, int E) {
    __shared__ int s_any;
    if (threadIdx.x == 0) s_any = 0;
    __syncthreads();
    int nchk = E < 1024 ? E : 1024;
    int acc = 0;
    for (int e = threadIdx.x; e < nchk; e += blockDim.x)
        acc |= ei[2 * e + 1];
    if (acc) atomicOr(&s_any, 1);
    __syncthreads();
    if (threadIdx.x == 0) g_is64 = (s_any ? 0 : 1);
}

__global__ void zero_deg_kernel(int n) {
    int i = blockIdx.x * blockDim.x + threadIdx.x;
    if (i < n) g_deg[i] = 0;
}

__global__ void hist_kernel(const int* __restrict__ ei, int E) {
    int e = blockIdx.x * blockDim.x + threadIdx.x;
    if (e >= E) return;
    int dst = g_is64 ? ei[2 * (E + e)] : ei[E + e];
    atomicAdd(&g_deg[dst], 1);
}

// scan stage A: per-block (1024 elems) sums
__global__ void scan_a_kernel(int n) {
    __shared__ int ssum[256];
    int tid = threadIdx.x;
    int base = blockIdx.x * 1024 + tid * 4;
    int s = 0;
#pragma unroll
    for (int j = 0; j < 4; ++j) {
        int i = base + j;
        if (i < n) s += g_deg[i];
    }
    ssum[tid] = s;
    __syncthreads();
    for (int off = 128; off > 0; off >>= 1) {
        if (tid < off) ssum[tid] += ssum[tid + off];
        __syncthreads();
    }
    if (tid == 0) g_bsum[blockIdx.x] = ssum[0];
}

// scan stage B: exclusive scan of block sums (single thread; nblk <= 128)
__global__ void scan_b_kernel(int nblk, int n) {
    if (threadIdx.x == 0 && blockIdx.x == 0) {
        int run = 0;
        for (int b = 0; b < nblk; ++b) {
            g_boff[b] = run;
            run += g_bsum[b];
        }
        g_off[n] = run;
    }
}

// scan stage C: per-block exclusive scan + offset; writes g_off and g_cursor
__global__ void scan_c_kernel(int n) {
    __shared__ int sdata[256];
    int tid = threadIdx.x;
    int base = blockIdx.x * 1024 + tid * 4;
    int v[4];
    int tsum = 0;
#pragma unroll
    for (int j = 0; j < 4; ++j) {
        int i = base + j;
        v[j] = (i < n) ? g_deg[i] : 0;
        tsum += v[j];
    }
    sdata[tid] = tsum;
    __syncthreads();
    for (int off = 1; off < 256; off <<= 1) {
        int t = (tid >= off) ? sdata[tid - off] : 0;
        __syncthreads();
        sdata[tid] += t;
        __syncthreads();
    }
    int excl = sdata[tid] - tsum + g_boff[blockIdx.x];
#pragma unroll
    for (int j = 0; j < 4; ++j) {
        int i = base + j;
        if (i < n) {
            g_off[i] = excl;
            g_cursor[i] = excl;
            excl += v[j];
        }
    }
}

__global__ void reorder_kernel(const int* __restrict__ ei, int E) {
    int e = blockIdx.x * blockDim.x + threadIdx.x;
    if (e >= E) return;
    int src, dst;
    if (g_is64) {
        src = ei[2 * e];
        dst = ei[2 * (E + e)];
    } else {
        src = ei[e];
        dst = ei[E + e];
    }
    int pos = atomicAdd(&g_cursor[dst], 1);
    g_ssrc[pos] = src;
}

// ---------------- mean aggregation: one warp per dst node, no atomics ----------------
__global__ void agg_kernel(const float* __restrict__ feat, int n) {
    int gid = blockIdx.x * blockDim.x + threadIdx.x;
    int d = gid >> 5, lane = gid & 31;
    if (d >= n) return;
    int s = g_off[d], e = g_off[d + 1];
    const float4* f4 = (const float4*)feat;
    float4 acc = make_float4(0.f, 0.f, 0.f, 0.f);
    int i = s;
    for (; i + 1 < e; i += 2) {
        int s0 = g_ssrc[i], s1 = g_ssrc[i + 1];
        float4 v0 = f4[(size_t)s0 * 32 + lane];
        float4 v1 = f4[(size_t)s1 * 32 + lane];
        acc.x += v0.x; acc.y += v0.y; acc.z += v0.z; acc.w += v0.w;
        acc.x += v1.x; acc.y += v1.y; acc.z += v1.z; acc.w += v1.w;
    }
    if (i < e) {
        int s0 = g_ssrc[i];
        float4 v0 = f4[(size_t)s0 * 32 + lane];
        acc.x += v0.x; acc.y += v0.y; acc.z += v0.z; acc.w += v0.w;
    }
    float inv = (e > s) ? 1.0f / (float)(e - s) : 0.0f;
    acc.x *= inv; acc.y *= inv; acc.z *= inv; acc.w *= inv;
    ((float4*)g_agg)[(size_t)d * 32 + lane] = acc;   // mean pre-folded
}

// ---------------- HMMA fused SAGE layer ----------------
// out = act( g_agg(mean) @ Wl^T + bl + A2 @ Wr^T ), split-bf16 3-term.
__device__ __forceinline__ void mma_pass(u32 abh, u32 abl, u32 wbh, u32 wbl,
                                         float acc[2][4][4],
                                         const u32* rowA256, u32 rowA7, u32 kbitA,
                                         const u32* rw256, const u32* rw7, u32 kgrpW) {
#pragma unroll
    for (int ks = 0; ks < 8; ++ks) {
        u32 ks2 = (u32)(ks << 1);
        u32 ah[2][4], al[2][4], wh[2][4], wl[2][4];
        u32 ca = ((ks2 | kbitA) ^ rowA7) << 4;
#pragma unroll
        for (int mt = 0; mt < 2; ++mt) {
            ldsm4(ah[mt], abh + rowA256[mt] + ca);
            ldsm4(al[mt], abl + rowA256[mt] + ca);
        }
#pragma unroll
        for (int nt2 = 0; nt2 < 2; ++nt2) {
            u32 cw = ((ks2 | kgrpW) ^ rw7[nt2]) << 4;
            ldsm4(wh[nt2], wbh + rw256[nt2] + cw);
            ldsm4(wl[nt2], wbl + rw256[nt2] + cw);
        }
#pragma unroll
        for (int mt = 0; mt < 2; ++mt) {
#pragma unroll
            for (int nt = 0; nt < 4; ++nt) {
                const u32* bh = &wh[nt >> 1][(nt & 1) * 2];
                const u32* bl2 = &wl[nt >> 1][(nt & 1) * 2];
                mma16816(acc[mt][nt], ah[mt], bh);
                mma16816(acc[mt][nt], ah[mt], bl2);
                mma16816(acc[mt][nt], al[mt], bh);
            }
        }
    }
}

__global__ void __launch_bounds__(256, 1)
layer_kernel(const float* __restrict__ A2,
             const float* __restrict__ Wl,
             const float* __restrict__ Wr,
             const float* __restrict__ bl,
             float* __restrict__ out,
             int n, int apply_sig, int ntiles) {
    extern __shared__ char sm[];
    u32 smb = smem_u32(sm);
    float* sBias = (float*)(sm + OFF_BIAS);
    int tid = threadIdx.x, wid = tid >> 5, lane = tid & 31;
    int warp_m = wid & 1, warp_n = wid >> 1;

    // Split both weight matrices ([n][k], 128x128) into bf16 hi/lo.
    for (int idx = tid; idx < 128 * 32; idx += 256) {
        int r = idx >> 5, q = idx & 31;
        split_store(sm + OFF_WLH, sm + OFF_WLL, r, q, ((const float4*)Wl)[idx]);
        split_store(sm + OFF_WRH, sm + OFF_WRL, r, q, ((const float4*)Wr)[idx]);
    }
    if (tid < 128) sBias[tid] = bl[tid];

    // ldmatrix address precomputation.
    u32 rowA256[2], rowA7;
    {
        int ra0 = warp_m * 32 + (lane & 15);
        rowA256[0] = (u32)(ra0 << 8);
        rowA256[1] = (u32)((ra0 + 16) << 8);
        rowA7 = (u32)(ra0 & 7);
    }
    u32 kbitA = (u32)(lane >> 4);
    u32 rw256[2], rw7[2];
    u32 kgrpW = (u32)((lane >> 3) & 1);
    {
        int base = warp_n * 32 + (lane & 7) + ((lane >> 4) << 3);
#pragma unroll
        for (int nt2 = 0; nt2 < 2; ++nt2) {
            int rw = base + nt2 * 16;
            rw256[nt2] = (u32)(rw << 8);
            rw7[nt2] = (u32)(rw & 7);
        }
    }
    int g = lane >> 2, c2 = (lane & 3) * 2;

    const float4* agg4 = (const float4*)g_agg;
    const float4* x4 = (const float4*)A2;

    for (int tile = blockIdx.x; tile < ntiles; tile += gridDim.x) {
        int row0 = tile * BM;

        __syncthreads();   // prior tile done reading A buffers (also covers W on 1st)

        // Load both passes' A tiles to registers (16 independent LDG.128).
        float4 va[8], vx[8];
        const float4 fz = make_float4(0.f, 0.f, 0.f, 0.f);
#pragma unroll
        for (int j = 0; j < 8; ++j) {
            int idx = tid + j * 256;
            int row = row0 + (idx >> 5);
            va[j] = (row < n) ? agg4[(size_t)row * 32 + (idx & 31)] : fz;
        }
#pragma unroll
        for (int j = 0; j < 8; ++j) {
            int idx = tid + j * 256;
            int row = row0 + (idx >> 5);
            vx[j] = (row < n) ? x4[(size_t)row * 32 + (idx & 31)] : fz;
        }
#pragma unroll
        for (int j = 0; j < 8; ++j) {
            int idx = tid + j * 256;
            int r = idx >> 5, q = idx & 31;
            split_store(sm + OFF_AGH, sm + OFF_AGL, r, q, va[j]);
            split_store(sm + OFF_AXH, sm + OFF_AXL, r, q, vx[j]);
        }
        __syncthreads();

        float acc[2][4][4];
#pragma unroll
        for (int mt = 0; mt < 2; ++mt)
#pragma unroll
            for (int nt = 0; nt < 4; ++nt)
#pragma unroll
                for (int i = 0; i < 4; ++i) acc[mt][nt][i] = 0.f;

        mma_pass(smb + OFF_AGH, smb + OFF_AGL, smb + OFF_WLH, smb + OFF_WLL,
                 acc, rowA256, rowA7, kbitA, rw256, rw7, kgrpW);
        mma_pass(smb + OFF_AXH, smb + OFF_AXL, smb + OFF_WRH, smb + OFF_WRL,
                 acc, rowA256, rowA7, kbitA, rw256, rw7, kgrpW);

        // epilogue
#pragma unroll
        for (int mt = 0; mt < 2; ++mt) {
#pragma unroll
            for (int half = 0; half < 2; ++half) {
                int row = row0 + warp_m * 32 + mt * 16 + g + half * 8;
                if (row < n) {
                    float* op = out + (size_t)row * CH + warp_n * 32 + c2;
#pragma unroll
                    for (int nt = 0; nt < 4; ++nt) {
                        int col = warp_n * 32 + nt * 8 + c2;
                        float2 v;
                        v.x = acc[mt][nt][half * 2 + 0] + sBias[col];
                        v.y = acc[mt][nt][half * 2 + 1] + sBias[col + 1];
                        if (apply_sig) {
                            v.x = 1.0f / (1.0f + __expf(-v.x));
                            v.y = 1.0f / (1.0f + __expf(-v.y));
                        }
                        *(float2*)(op + nt * 8) = v;
                    }
                }
            }
        }
    }
}

extern "C" void kernel_launch(void* const* d_in, const int* in_sizes, int n_in,
                              void* d_out, int out_size) {
    const float* x   = (const float*)d_in[0];
    const int*   ei  = (const int*)d_in[1];
    const float* W1l = (const float*)d_in[2];
    const float* b1l = (const float*)d_in[3];
    const float* W1r = (const float*)d_in[4];
    const float* W2l = (const float*)d_in[5];
    const float* b2l = (const float*)d_in[6];
    const float* W2r = (const float*)d_in[7];
    float* out = (float*)d_out;

    int n = in_sizes[0] / CH;   // 100000
    int E = in_sizes[1] / 2;    // 625000
    if (E > EMAX) E = EMAX;

    float* h_ptr = nullptr;
    cudaGetSymbolAddress((void**)&h_ptr, g_h);

    cudaFuncSetAttribute(layer_kernel,
                         cudaFuncAttributeMaxDynamicSharedMemorySize, SMEM_TOTAL);

    int ntiles = (n + BM - 1) / BM;
    int grid_layer = ntiles < 148 ? ntiles : 148;
    int grid_edge = (E + 255) / 256;
    int nblk = (n + 1023) / 1024;
    int grid_agg = (int)(((long long)n * 32 + 255) / 256);

    // CSR preprocessing (once; reused by both layers)
    detect_kernel<<<1, 256>>>(ei, E);
    zero_deg_kernel<<<(n + 255) / 256, 256>>>(n);
    hist_kernel<<<grid_edge, 256>>>(ei, E);
    scan_a_kernel<<<nblk, 256>>>(n);
    scan_b_kernel<<<1, 32>>>(nblk, n);
    scan_c_kernel<<<nblk, 256>>>(n);
    reorder_kernel<<<grid_edge, 256>>>(ei, E);

    // Layer 1
    agg_kernel<<<grid_agg, 256>>>(x, n);
    layer_kernel<<<grid_layer, 256, SMEM_TOTAL>>>(x, W1l, W1r, b1l, h_ptr, n, 1, ntiles);

    // Layer 2
    agg_kernel<<<grid_agg, 256>>>(h_ptr, n);
    layer_kernel<<<grid_layer, 256, SMEM_TOTAL>>>(h_ptr, W2l, W2r, b2l, out, n, 0, ntiles);
}

// round 6
// speedup vs baseline: 3.0373x; 1.1285x over previous
#include <cuda_runtime.h>
#include <cuda_bf16.h>

#define NN 100000
#define EMAX 700000
#define CH 128
#define BM 64

typedef unsigned long long ull;
typedef unsigned int u32;

// ---- smem byte offsets (layer kernel) ----
#define OFF_BIAS 0
#define OFF_WLH 512
#define OFF_WLL (OFF_WLH + 32768)
#define OFF_WRH (OFF_WLL + 32768)
#define OFF_WRL (OFF_WRH + 32768)
#define OFF_AGH (OFF_WRL + 32768)
#define OFF_AGL (OFF_AGH + 16384)
#define OFF_AXH (OFF_AGL + 16384)
#define OFF_AXL (OFF_AXH + 16384)
#define SMEM_TOTAL (OFF_AXL + 16384)   // 197120 bytes

__device__ __align__(128) float g_agg[(size_t)NN * CH];
__device__ __align__(128) float g_h[(size_t)NN * CH];
__device__ int g_deg[NN];
__device__ int g_off[NN + 1];
__device__ int g_cursor[NN];
__device__ int g_bsum[128];
__device__ int g_boff[128];
__device__ int g_ssrc[EMAX];
__device__ int g_is64;

// ---------------- helpers ----------------
__device__ __forceinline__ u32 smem_u32(const void* p) {
    u32 a;
    asm("{ .reg .u64 t; cvta.to.shared.u64 t, %1; cvt.u32.u64 %0, t; }"
        : "=r"(a) : "l"(p));
    return a;
}
__device__ __forceinline__ void ldsm4(u32* r, u32 addr) {
    asm volatile("ldmatrix.sync.aligned.m8n8.x4.shared.b16 {%0,%1,%2,%3}, [%4];"
                 : "=r"(r[0]), "=r"(r[1]), "=r"(r[2]), "=r"(r[3]) : "r"(addr));
}
__device__ __forceinline__ void mma16816(float* d, const u32* a, const u32* b) {
    asm volatile(
        "mma.sync.aligned.m16n8k16.row.col.f32.bf16.bf16.f32 "
        "{%0,%1,%2,%3}, {%4,%5,%6,%7}, {%8,%9}, {%0,%1,%2,%3};"
        : "+f"(d[0]), "+f"(d[1]), "+f"(d[2]), "+f"(d[3])
        : "r"(a[0]), "r"(a[1]), "r"(a[2]), "r"(a[3]), "r"(b[0]), "r"(b[1]));
}
__device__ __forceinline__ ull pack4bf(__nv_bfloat16 a, __nv_bfloat16 b,
                                       __nv_bfloat16 c, __nv_bfloat16 d) {
    u32 lo = ((u32)__bfloat16_as_ushort(b) << 16) | __bfloat16_as_ushort(a);
    u32 hi = ((u32)__bfloat16_as_ushort(d) << 16) | __bfloat16_as_ushort(c);
    return ((ull)hi << 32) | lo;
}
// byte offset of 4 bf16 at (row r, float4-col q); 256B rows, 16B-chunk XOR swizzle.
__device__ __forceinline__ u32 swz_off(int r, int q) {
    return ((u32)r << 8) + ((u32)(((q >> 1) ^ (r & 7))) << 4) + ((u32)(q & 1) << 3);
}
__device__ __forceinline__ void split_store(char* hi, char* lo, int r, int q, float4 v) {
    __nv_bfloat16 hx = __float2bfloat16_rn(v.x);
    __nv_bfloat16 hy = __float2bfloat16_rn(v.y);
    __nv_bfloat16 hz = __float2bfloat16_rn(v.z);
    __nv_bfloat16 hw = __float2bfloat16_rn(v.w);
    u32 off = swz_off(r, q);
    *(ull*)(hi + off) = pack4bf(hx, hy, hz, hw);
    *(ull*)(lo + off) = pack4bf(
        __float2bfloat16_rn(v.x - __bfloat162float(hx)),
        __float2bfloat16_rn(v.y - __bfloat162float(hy)),
        __float2bfloat16_rn(v.z - __bfloat162float(hz)),
        __float2bfloat16_rn(v.w - __bfloat162float(hw)));
}

// ---------------- graph preprocessing (CSR by dst, once per replay) ----------------
// zero degree array; block 0 also detects int64 vs int32 edge_index.
__global__ void zero_detect_kernel(const int* __restrict__ ei, int E, int n) {
    int i = blockIdx.x * blockDim.x + threadIdx.x;
    if (i < n) g_deg[i] = 0;
    if (blockIdx.x == 0) {
        __shared__ int s_any;
        if (threadIdx.x == 0) s_any = 0;
        __syncthreads();
        int nchk = E < 1024 ? E : 1024;
        int acc = 0;
        for (int e = threadIdx.x; e < nchk; e += blockDim.x)
            acc |= ei[2 * e + 1];
        if (acc) atomicOr(&s_any, 1);
        __syncthreads();
        if (threadIdx.x == 0) g_is64 = (s_any ? 0 : 1);
    }
}

__global__ void hist_kernel(const int* __restrict__ ei, int E) {
    int e = blockIdx.x * blockDim.x + threadIdx.x;
    if (e >= E) return;
    int dst = g_is64 ? ei[2 * (E + e)] : ei[E + e];
    atomicAdd(&g_deg[dst], 1);
}

// scan stage A: per-block (1024 elems) sums
__global__ void scan_a_kernel(int n) {
    __shared__ int ssum[256];
    int tid = threadIdx.x;
    int base = blockIdx.x * 1024 + tid * 4;
    int s = 0;
#pragma unroll
    for (int j = 0; j < 4; ++j) {
        int i = base + j;
        if (i < n) s += g_deg[i];
    }
    ssum[tid] = s;
    __syncthreads();
    for (int off = 128; off > 0; off >>= 1) {
        if (tid < off) ssum[tid] += ssum[tid + off];
        __syncthreads();
    }
    if (tid == 0) g_bsum[blockIdx.x] = ssum[0];
}

// scan stage B: parallel exclusive scan of <=128 block sums
__global__ void scan_b_kernel(int nblk, int n) {
    __shared__ int s[128];
    int tid = threadIdx.x;
    int v = (tid < nblk) ? g_bsum[tid] : 0;
    s[tid] = v;
    __syncthreads();
    for (int off = 1; off < 128; off <<= 1) {
        int t = (tid >= off) ? s[tid - off] : 0;
        __syncthreads();
        s[tid] += t;
        __syncthreads();
    }
    if (tid < nblk) g_boff[tid] = s[tid] - v;
    if (tid == nblk - 1) g_off[n] = s[tid];
}

// scan stage C: per-block exclusive scan + offset; writes g_off and g_cursor
__global__ void scan_c_kernel(int n) {
    __shared__ int sdata[256];
    int tid = threadIdx.x;
    int base = blockIdx.x * 1024 + tid * 4;
    int v[4];
    int tsum = 0;
#pragma unroll
    for (int j = 0; j < 4; ++j) {
        int i = base + j;
        v[j] = (i < n) ? g_deg[i] : 0;
        tsum += v[j];
    }
    sdata[tid] = tsum;
    __syncthreads();
    for (int off = 1; off < 256; off <<= 1) {
        int t = (tid >= off) ? sdata[tid - off] : 0;
        __syncthreads();
        sdata[tid] += t;
        __syncthreads();
    }
    int excl = sdata[tid] - tsum + g_boff[blockIdx.x];
#pragma unroll
    for (int j = 0; j < 4; ++j) {
        int i = base + j;
        if (i < n) {
            g_off[i] = excl;
            g_cursor[i] = excl;
            excl += v[j];
        }
    }
}

__global__ void reorder_kernel(const int* __restrict__ ei, int E) {
    int e = blockIdx.x * blockDim.x + threadIdx.x;
    if (e >= E) return;
    int src, dst;
    if (g_is64) {
        src = ei[2 * e];
        dst = ei[2 * (E + e)];
    } else {
        src = ei[e];
        dst = ei[E + e];
    }
    int pos = atomicAdd(&g_cursor[dst], 1);
    g_ssrc[pos] = src;
}

// ---------------- mean aggregation: one warp per dst node, no atomics ----------------
__global__ void agg_kernel(const float* __restrict__ feat, int n) {
    int gid = blockIdx.x * blockDim.x + threadIdx.x;
    int d = gid >> 5, lane = gid & 31;
    if (d >= n) return;
    int s = g_off[d], e = g_off[d + 1];
    const float4* f4 = (const float4*)feat;
    float4 acc = make_float4(0.f, 0.f, 0.f, 0.f);
    int i = s;
    for (; i + 3 < e; i += 4) {
        int s0 = g_ssrc[i], s1 = g_ssrc[i + 1], s2 = g_ssrc[i + 2], s3 = g_ssrc[i + 3];
        float4 v0 = f4[(size_t)s0 * 32 + lane];
        float4 v1 = f4[(size_t)s1 * 32 + lane];
        float4 v2 = f4[(size_t)s2 * 32 + lane];
        float4 v3 = f4[(size_t)s3 * 32 + lane];
        acc.x += v0.x; acc.y += v0.y; acc.z += v0.z; acc.w += v0.w;
        acc.x += v1.x; acc.y += v1.y; acc.z += v1.z; acc.w += v1.w;
        acc.x += v2.x; acc.y += v2.y; acc.z += v2.z; acc.w += v2.w;
        acc.x += v3.x; acc.y += v3.y; acc.z += v3.z; acc.w += v3.w;
    }
    for (; i < e; ++i) {
        int s0 = g_ssrc[i];
        float4 v0 = f4[(size_t)s0 * 32 + lane];
        acc.x += v0.x; acc.y += v0.y; acc.z += v0.z; acc.w += v0.w;
    }
    float inv = (e > s) ? 1.0f / (float)(e - s) : 0.0f;
    acc.x *= inv; acc.y *= inv; acc.z *= inv; acc.w *= inv;
    ((float4*)g_agg)[(size_t)d * 32 + lane] = acc;   // mean pre-folded
}

// ---------------- HMMA fused SAGE layer (software-pipelined) ----------------
// out = act( g_agg(mean) @ Wl^T + bl + A2 @ Wr^T ), split-bf16 3-term.
__device__ __forceinline__ void mma_pass(u32 abh, u32 abl, u32 wbh, u32 wbl,
                                         float acc[2][4][4],
                                         const u32* rowA256, u32 rowA7, u32 kbitA,
                                         const u32* rw256, const u32* rw7, u32 kgrpW) {
#pragma unroll
    for (int ks = 0; ks < 8; ++ks) {
        u32 ks2 = (u32)(ks << 1);
        u32 ah[2][4], al[2][4], wh[2][4], wl[2][4];
        u32 ca = ((ks2 | kbitA) ^ rowA7) << 4;
#pragma unroll
        for (int mt = 0; mt < 2; ++mt) {
            ldsm4(ah[mt], abh + rowA256[mt] + ca);
            ldsm4(al[mt], abl + rowA256[mt] + ca);
        }
#pragma unroll
        for (int nt2 = 0; nt2 < 2; ++nt2) {
            u32 cw = ((ks2 | kgrpW) ^ rw7[nt2]) << 4;
            ldsm4(wh[nt2], wbh + rw256[nt2] + cw);
            ldsm4(wl[nt2], wbl + rw256[nt2] + cw);
        }
#pragma unroll
        for (int mt = 0; mt < 2; ++mt) {
#pragma unroll
            for (int nt = 0; nt < 4; ++nt) {
                const u32* bh = &wh[nt >> 1][(nt & 1) * 2];
                const u32* bl2 = &wl[nt >> 1][(nt & 1) * 2];
                mma16816(acc[mt][nt], ah[mt], bh);
                mma16816(acc[mt][nt], ah[mt], bl2);
                mma16816(acc[mt][nt], al[mt], bh);
            }
        }
    }
}

__global__ void __launch_bounds__(256, 1)
layer_kernel(const float* __restrict__ A2,
             const float* __restrict__ Wl,
             const float* __restrict__ Wr,
             const float* __restrict__ bl,
             float* __restrict__ out,
             int n, int apply_sig, int ntiles) {
    extern __shared__ char sm[];
    u32 smb = smem_u32(sm);
    float* sBias = (float*)(sm + OFF_BIAS);
    int tid = threadIdx.x, wid = tid >> 5, lane = tid & 31;
    int warp_m = wid & 1, warp_n = wid >> 1;

    // Split both weight matrices ([n][k], 128x128) into bf16 hi/lo.
    for (int idx = tid; idx < 128 * 32; idx += 256) {
        int r = idx >> 5, q = idx & 31;
        split_store(sm + OFF_WLH, sm + OFF_WLL, r, q, ((const float4*)Wl)[idx]);
        split_store(sm + OFF_WRH, sm + OFF_WRL, r, q, ((const float4*)Wr)[idx]);
    }
    if (tid < 128) sBias[tid] = bl[tid];

    // ldmatrix address precomputation.
    u32 rowA256[2], rowA7;
    {
        int ra0 = warp_m * 32 + (lane & 15);
        rowA256[0] = (u32)(ra0 << 8);
        rowA256[1] = (u32)((ra0 + 16) << 8);
        rowA7 = (u32)(ra0 & 7);
    }
    u32 kbitA = (u32)(lane >> 4);
    u32 rw256[2], rw7[2];
    u32 kgrpW = (u32)((lane >> 3) & 1);
    {
        int base = warp_n * 32 + (lane & 7) + ((lane >> 4) << 3);
#pragma unroll
        for (int nt2 = 0; nt2 < 2; ++nt2) {
            int rw = base + nt2 * 16;
            rw256[nt2] = (u32)(rw << 8);
            rw7[nt2] = (u32)(rw & 7);
        }
    }
    int g = lane >> 2, c2 = (lane & 3) * 2;

    const float4* agg4 = (const float4*)g_agg;
    const float4* x4 = (const float4*)A2;
    const float4 fz = make_float4(0.f, 0.f, 0.f, 0.f);

    float4 va[8], vx[8];
    int tile = blockIdx.x;

    // Preload first tile's A registers (overlaps with weight-split smem stores).
    if (tile < ntiles) {
        int row0 = tile * BM;
#pragma unroll
        for (int j = 0; j < 8; ++j) {
            int idx = tid + j * 256;
            int row = row0 + (idx >> 5);
            va[j] = (row < n) ? agg4[(size_t)row * 32 + (idx & 31)] : fz;
            vx[j] = (row < n) ? x4[(size_t)row * 32 + (idx & 31)] : fz;
        }
    }

    for (; tile < ntiles; tile += gridDim.x) {
        __syncthreads();   // prior tile MMA done reading A buffers (covers W on 1st)
#pragma unroll
        for (int j = 0; j < 8; ++j) {
            int idx = tid + j * 256;
            int r = idx >> 5, q = idx & 31;
            split_store(sm + OFF_AGH, sm + OFF_AGL, r, q, va[j]);
            split_store(sm + OFF_AXH, sm + OFF_AXL, r, q, vx[j]);
        }
        __syncthreads();

        // Prefetch next tile's A registers; LDG latency hides under MMA below.
        int next = tile + gridDim.x;
        if (next < ntiles) {
            int row0 = next * BM;
#pragma unroll
            for (int j = 0; j < 8; ++j) {
                int idx = tid + j * 256;
                int row = row0 + (idx >> 5);
                va[j] = (row < n) ? agg4[(size_t)row * 32 + (idx & 31)] : fz;
                vx[j] = (row < n) ? x4[(size_t)row * 32 + (idx & 31)] : fz;
            }
        }

        float acc[2][4][4];
#pragma unroll
        for (int mt = 0; mt < 2; ++mt)
#pragma unroll
            for (int nt = 0; nt < 4; ++nt)
#pragma unroll
                for (int i = 0; i < 4; ++i) acc[mt][nt][i] = 0.f;

        mma_pass(smb + OFF_AGH, smb + OFF_AGL, smb + OFF_WLH, smb + OFF_WLL,
                 acc, rowA256, rowA7, kbitA, rw256, rw7, kgrpW);
        mma_pass(smb + OFF_AXH, smb + OFF_AXL, smb + OFF_WRH, smb + OFF_WRL,
                 acc, rowA256, rowA7, kbitA, rw256, rw7, kgrpW);

        // epilogue
        int row0 = tile * BM;
#pragma unroll
        for (int mt = 0; mt < 2; ++mt) {
#pragma unroll
            for (int half = 0; half < 2; ++half) {
                int row = row0 + warp_m * 32 + mt * 16 + g + half * 8;
                if (row < n) {
                    float* op = out + (size_t)row * CH + warp_n * 32 + c2;
#pragma unroll
                    for (int nt = 0; nt < 4; ++nt) {
                        int col = warp_n * 32 + nt * 8 + c2;
                        float2 v;
                        v.x = acc[mt][nt][half * 2 + 0] + sBias[col];
                        v.y = acc[mt][nt][half * 2 + 1] + sBias[col + 1];
                        if (apply_sig) {
                            v.x = 1.0f / (1.0f + __expf(-v.x));
                            v.y = 1.0f / (1.0f + __expf(-v.y));
                        }
                        *(float2*)(op + nt * 8) = v;
                    }
                }
            }
        }
    }
}

extern "C" void kernel_launch(void* const* d_in, const int* in_sizes, int n_in,
                              void* d_out, int out_size) {
    const float* x   = (const float*)d_in[0];
    const int*   ei  = (const int*)d_in[1];
    const float* W1l = (const float*)d_in[2];
    const float* b1l = (const float*)d_in[3];
    const float* W1r = (const float*)d_in[4];
    const float* W2l = (const float*)d_in[5];
    const float* b2l = (const float*)d_in[6];
    const float* W2r = (const float*)d_in[7];
    float* out = (float*)d_out;

    int n = in_sizes[0] / CH;   // 100000
    int E = in_sizes[1] / 2;    // 625000
    if (E > EMAX) E = EMAX;

    float* h_ptr = nullptr;
    cudaGetSymbolAddress((void**)&h_ptr, g_h);

    cudaFuncSetAttribute(layer_kernel,
                         cudaFuncAttributeMaxDynamicSharedMemorySize, SMEM_TOTAL);

    int ntiles = (n + BM - 1) / BM;
    int grid_layer = ntiles < 148 ? ntiles : 148;
    int grid_edge = (E + 255) / 256;
    int nblk = (n + 1023) / 1024;
    int grid_agg = (int)(((long long)n * 32 + 255) / 256);

    // CSR preprocessing (once; reused by both layers)
    zero_detect_kernel<<<(n + 255) / 256, 256>>>(ei, E, n);
    hist_kernel<<<grid_edge, 256>>>(ei, E);
    scan_a_kernel<<<nblk, 256>>>(n);
    scan_b_kernel<<<1, 128>>>(nblk, n);
    scan_c_kernel<<<nblk, 256>>>(n);
    reorder_kernel<<<grid_edge, 256>>>(ei, E);

    // Layer 1
    agg_kernel<<<grid_agg, 256>>>(x, n);
    layer_kernel<<<grid_layer, 256, SMEM_TOTAL>>>(x, W1l, W1r, b1l, h_ptr, n, 1, ntiles);

    // Layer 2
    agg_kernel<<<grid_agg, 256>>>(h_ptr, n);
    layer_kernel<<<grid_layer, 256, SMEM_TOTAL>>>(h_ptr, W2l, W2r, b2l, out, n, 0, ntiles);
}

// round 7
// speedup vs baseline: 3.5022x; 1.1531x over previous
#include <cuda_runtime.h>
#include <cuda_fp16.h>

#define NN 100000
#define EMAX 700000
#define CH 128
#define BM 64

typedef unsigned long long ull;
typedef unsigned int u32;

// ---- smem byte offsets (layer kernel) ----
#define OFF_BIAS 0
#define OFF_WLH 512
#define OFF_WRH (OFF_WLH + 32768)
#define OFF_AGH (OFF_WRH + 32768)
#define OFF_AGL (OFF_AGH + 16384)
#define OFF_AXH (OFF_AGL + 16384)
#define OFF_AXL (OFF_AXH + 16384)
#define SMEM_TOTAL (OFF_AXL + 16384)   // 131584 bytes

__device__ __align__(128) float g_agg[(size_t)NN * CH];
__device__ __align__(128) float g_h[(size_t)NN * CH];
__device__ int g_deg[NN];
__device__ int g_off[NN + 1];
__device__ int g_cursor[NN];
__device__ int g_bsum[128];
__device__ int g_ssrc[EMAX];
__device__ int g_is64;

// ---------------- helpers ----------------
__device__ __forceinline__ u32 smem_u32(const void* p) {
    u32 a;
    asm("{ .reg .u64 t; cvta.to.shared.u64 t, %1; cvt.u32.u64 %0, t; }"
        : "=r"(a) : "l"(p));
    return a;
}
__device__ __forceinline__ void ldsm4(u32* r, u32 addr) {
    asm volatile("ldmatrix.sync.aligned.m8n8.x4.shared.b16 {%0,%1,%2,%3}, [%4];"
                 : "=r"(r[0]), "=r"(r[1]), "=r"(r[2]), "=r"(r[3]) : "r"(addr));
}
__device__ __forceinline__ void mma16816(float* d, const u32* a, const u32* b) {
    asm volatile(
        "mma.sync.aligned.m16n8k16.row.col.f32.f16.f16.f32 "
        "{%0,%1,%2,%3}, {%4,%5,%6,%7}, {%8,%9}, {%0,%1,%2,%3};"
        : "+f"(d[0]), "+f"(d[1]), "+f"(d[2]), "+f"(d[3])
        : "r"(a[0]), "r"(a[1]), "r"(a[2]), "r"(a[3]), "r"(b[0]), "r"(b[1]));
}
__device__ __forceinline__ ull pack4h(__half a, __half b, __half c, __half d) {
    u32 lo = ((u32)__half_as_ushort(b) << 16) | __half_as_ushort(a);
    u32 hi = ((u32)__half_as_ushort(d) << 16) | __half_as_ushort(c);
    return ((ull)hi << 32) | lo;
}
// byte offset of 4 fp16 at (row r, float4-col q); 256B rows, 16B-chunk XOR swizzle.
__device__ __forceinline__ u32 swz_off(int r, int q) {
    return ((u32)r << 8) + ((u32)(((q >> 1) ^ (r & 7))) << 4) + ((u32)(q & 1) << 3);
}
// A-side: exact 2-way fp16 split (hi + residual lo).
__device__ __forceinline__ void split_store_a(char* hi, char* lo, int r, int q, float4 v) {
    __half hx = __float2half_rn(v.x);
    __half hy = __float2half_rn(v.y);
    __half hz = __float2half_rn(v.z);
    __half hw = __float2half_rn(v.w);
    u32 off = swz_off(r, q);
    *(ull*)(hi + off) = pack4h(hx, hy, hz, hw);
    *(ull*)(lo + off) = pack4h(
        __float2half_rn(v.x - __half2float(hx)),
        __float2half_rn(v.y - __half2float(hy)),
        __float2half_rn(v.z - __half2float(hz)),
        __float2half_rn(v.w - __half2float(hw)));
}
// W-side: single fp16 rounding.
__device__ __forceinline__ void round_store_w(char* hi, int r, int q, float4 v) {
    *(ull*)(hi + swz_off(r, q)) = pack4h(
        __float2half_rn(v.x), __float2half_rn(v.y),
        __float2half_rn(v.z), __float2half_rn(v.w));
}

// ---------------- graph preprocessing (CSR by dst, once per replay) ----------------
__global__ void zero_detect_kernel(const int* __restrict__ ei, int E, int n) {
    int i = blockIdx.x * blockDim.x + threadIdx.x;
    if (i < n) g_deg[i] = 0;
    if (blockIdx.x == 0) {
        __shared__ int s_any;
        if (threadIdx.x == 0) s_any = 0;
        __syncthreads();
        int nchk = E < 1024 ? E : 1024;
        int acc = 0;
        for (int e = threadIdx.x; e < nchk; e += blockDim.x)
            acc |= ei[2 * e + 1];
        if (acc) atomicOr(&s_any, 1);
        __syncthreads();
        if (threadIdx.x == 0) g_is64 = (s_any ? 0 : 1);
    }
}

__global__ void hist_kernel(const int* __restrict__ ei, int E) {
    int e = blockIdx.x * blockDim.x + threadIdx.x;
    if (e >= E) return;
    int dst = g_is64 ? ei[2 * (E + e)] : ei[E + e];
    atomicAdd(&g_deg[dst], 1);
}

// scan stage A: per-block (1024 elems) sums
__global__ void scan_a_kernel(int n) {
    __shared__ int ssum[256];
    int tid = threadIdx.x;
    int base = blockIdx.x * 1024 + tid * 4;
    int s = 0;
#pragma unroll
    for (int j = 0; j < 4; ++j) {
        int i = base + j;
        if (i < n) s += g_deg[i];
    }
    ssum[tid] = s;
    __syncthreads();
    for (int off = 128; off > 0; off >>= 1) {
        if (tid < off) ssum[tid] += ssum[tid + off];
        __syncthreads();
    }
    if (tid == 0) g_bsum[blockIdx.x] = ssum[0];
}

// scan stage C: per-block computes its own block-sum prefix (<=128 sums),
// then exclusive scan + offset; writes g_off, g_cursor, and g_off[n].
__global__ void scan_c_kernel(int n) {
    __shared__ int sdata[256];
    __shared__ int s_boff;
    int tid = threadIdx.x;

    // prefix of preceding block sums
    int partial = 0;
    for (int b = tid; b < (int)blockIdx.x; b += 256) partial += g_bsum[b];
    sdata[tid] = partial;
    __syncthreads();
    for (int off = 128; off > 0; off >>= 1) {
        if (tid < off) sdata[tid] += sdata[tid + off];
        __syncthreads();
    }
    if (tid == 0) s_boff = sdata[0];
    __syncthreads();

    int base = blockIdx.x * 1024 + tid * 4;
    int v[4];
    int tsum = 0;
#pragma unroll
    for (int j = 0; j < 4; ++j) {
        int i = base + j;
        v[j] = (i < n) ? g_deg[i] : 0;
        tsum += v[j];
    }
    sdata[tid] = tsum;
    __syncthreads();
    for (int off = 1; off < 256; off <<= 1) {
        int t = (tid >= off) ? sdata[tid - off] : 0;
        __syncthreads();
        sdata[tid] += t;
        __syncthreads();
    }
    int excl = sdata[tid] - tsum + s_boff;
#pragma unroll
    for (int j = 0; j < 4; ++j) {
        int i = base + j;
        if (i < n) {
            g_off[i] = excl;
            g_cursor[i] = excl;
            excl += v[j];
        }
    }
    if (blockIdx.x == gridDim.x - 1 && tid == 255)
        g_off[n] = s_boff + sdata[255];
}

__global__ void reorder_kernel(const int* __restrict__ ei, int E) {
    int e = blockIdx.x * blockDim.x + threadIdx.x;
    if (e >= E) return;
    int src, dst;
    if (g_is64) {
        src = ei[2 * e];
        dst = ei[2 * (E + e)];
    } else {
        src = ei[e];
        dst = ei[E + e];
    }
    int pos = atomicAdd(&g_cursor[dst], 1);
    g_ssrc[pos] = src;
}

// ---------------- mean aggregation: one warp per dst node, no atomics ----------------
__global__ void agg_kernel(const float* __restrict__ feat, int n) {
    int gid = blockIdx.x * blockDim.x + threadIdx.x;
    int d = gid >> 5, lane = gid & 31;
    if (d >= n) return;
    int s = g_off[d], e = g_off[d + 1];
    const float4* f4 = (const float4*)feat;
    float4 acc = make_float4(0.f, 0.f, 0.f, 0.f);
    int i = s;
    for (; i + 3 < e; i += 4) {
        int s0 = g_ssrc[i], s1 = g_ssrc[i + 1], s2 = g_ssrc[i + 2], s3 = g_ssrc[i + 3];
        float4 v0 = f4[(size_t)s0 * 32 + lane];
        float4 v1 = f4[(size_t)s1 * 32 + lane];
        float4 v2 = f4[(size_t)s2 * 32 + lane];
        float4 v3 = f4[(size_t)s3 * 32 + lane];
        acc.x += v0.x; acc.y += v0.y; acc.z += v0.z; acc.w += v0.w;
        acc.x += v1.x; acc.y += v1.y; acc.z += v1.z; acc.w += v1.w;
        acc.x += v2.x; acc.y += v2.y; acc.z += v2.z; acc.w += v2.w;
        acc.x += v3.x; acc.y += v3.y; acc.z += v3.z; acc.w += v3.w;
    }
    for (; i < e; ++i) {
        int s0 = g_ssrc[i];
        float4 v0 = f4[(size_t)s0 * 32 + lane];
        acc.x += v0.x; acc.y += v0.y; acc.z += v0.z; acc.w += v0.w;
    }
    float inv = (e > s) ? 1.0f / (float)(e - s) : 0.0f;
    acc.x *= inv; acc.y *= inv; acc.z *= inv; acc.w *= inv;
    ((float4*)g_agg)[(size_t)d * 32 + lane] = acc;   // mean pre-folded
}

// ---------------- HMMA fused SAGE layer (fp16 2-term split, pipelined) ----------------
// out = act( g_agg(mean) @ Wl^T + bl + A2 @ Wr^T )
// A = ah + al (exact fp16 split); W ~= wh (fp16). acc += ah*wh + al*wh.
__device__ __forceinline__ void mma_pass(u32 abh, u32 abl, u32 wbh,
                                         float acc[2][4][4],
                                         const u32* rowA256, u32 rowA7, u32 kbitA,
                                         const u32* rw256, const u32* rw7, u32 kgrpW) {
#pragma unroll
    for (int ks = 0; ks < 8; ++ks) {
        u32 ks2 = (u32)(ks << 1);
        u32 ah[2][4], al[2][4], wh[2][4];
        u32 ca = ((ks2 | kbitA) ^ rowA7) << 4;
#pragma unroll
        for (int mt = 0; mt < 2; ++mt) {
            ldsm4(ah[mt], abh + rowA256[mt] + ca);
            ldsm4(al[mt], abl + rowA256[mt] + ca);
        }
#pragma unroll
        for (int nt2 = 0; nt2 < 2; ++nt2) {
            u32 cw = ((ks2 | kgrpW) ^ rw7[nt2]) << 4;
            ldsm4(wh[nt2], wbh + rw256[nt2] + cw);
        }
#pragma unroll
        for (int mt = 0; mt < 2; ++mt) {
#pragma unroll
            for (int nt = 0; nt < 4; ++nt) {
                const u32* bh = &wh[nt >> 1][(nt & 1) * 2];
                mma16816(acc[mt][nt], ah[mt], bh);
                mma16816(acc[mt][nt], al[mt], bh);
            }
        }
    }
}

__global__ void __launch_bounds__(256, 1)
layer_kernel(const float* __restrict__ A2,
             const float* __restrict__ Wl,
             const float* __restrict__ Wr,
             const float* __restrict__ bl,
             float* __restrict__ out,
             int n, int apply_sig, int ntiles) {
    extern __shared__ char sm[];
    u32 smb = smem_u32(sm);
    float* sBias = (float*)(sm + OFF_BIAS);
    int tid = threadIdx.x, wid = tid >> 5, lane = tid & 31;
    int warp_m = wid & 1, warp_n = wid >> 1;

    // Round both weight matrices ([n][k], 128x128) to fp16.
    for (int idx = tid; idx < 128 * 32; idx += 256) {
        int r = idx >> 5, q = idx & 31;
        round_store_w(sm + OFF_WLH, r, q, ((const float4*)Wl)[idx]);
        round_store_w(sm + OFF_WRH, r, q, ((const float4*)Wr)[idx]);
    }
    if (tid < 128) sBias[tid] = bl[tid];

    // ldmatrix address precomputation.
    u32 rowA256[2], rowA7;
    {
        int ra0 = warp_m * 32 + (lane & 15);
        rowA256[0] = (u32)(ra0 << 8);
        rowA256[1] = (u32)((ra0 + 16) << 8);
        rowA7 = (u32)(ra0 & 7);
    }
    u32 kbitA = (u32)(lane >> 4);
    u32 rw256[2], rw7[2];
    u32 kgrpW = (u32)((lane >> 3) & 1);
    {
        int base = warp_n * 32 + (lane & 7) + ((lane >> 4) << 3);
#pragma unroll
        for (int nt2 = 0; nt2 < 2; ++nt2) {
            int rw = base + nt2 * 16;
            rw256[nt2] = (u32)(rw << 8);
            rw7[nt2] = (u32)(rw & 7);
        }
    }
    int g = lane >> 2, c2 = (lane & 3) * 2;

    const float4* agg4 = (const float4*)g_agg;
    const float4* x4 = (const float4*)A2;
    const float4 fz = make_float4(0.f, 0.f, 0.f, 0.f);

    float4 va[8], vx[8];
    int tile = blockIdx.x;

    // Preload first tile's A registers (overlaps with weight smem stores).
    if (tile < ntiles) {
        int row0 = tile * BM;
#pragma unroll
        for (int j = 0; j < 8; ++j) {
            int idx = tid + j * 256;
            int row = row0 + (idx >> 5);
            va[j] = (row < n) ? agg4[(size_t)row * 32 + (idx & 31)] : fz;
            vx[j] = (row < n) ? x4[(size_t)row * 32 + (idx & 31)] : fz;
        }
    }

    for (; tile < ntiles; tile += gridDim.x) {
        __syncthreads();   // prior tile MMA done reading A buffers (covers W on 1st)
#pragma unroll
        for (int j = 0; j < 8; ++j) {
            int idx = tid + j * 256;
            int r = idx >> 5, q = idx & 31;
            split_store_a(sm + OFF_AGH, sm + OFF_AGL, r, q, va[j]);
            split_store_a(sm + OFF_AXH, sm + OFF_AXL, r, q, vx[j]);
        }
        __syncthreads();

        // Prefetch next tile's A registers; LDG latency hides under MMA below.
        int next = tile + gridDim.x;
        if (next < ntiles) {
            int row0 = next * BM;
#pragma unroll
            for (int j = 0; j < 8; ++j) {
                int idx = tid + j * 256;
                int row = row0 + (idx >> 5);
                va[j] = (row < n) ? agg4[(size_t)row * 32 + (idx & 31)] : fz;
                vx[j] = (row < n) ? x4[(size_t)row * 32 + (idx & 31)] : fz;
            }
        }

        float acc[2][4][4];
#pragma unroll
        for (int mt = 0; mt < 2; ++mt)
#pragma unroll
            for (int nt = 0; nt < 4; ++nt)
#pragma unroll
                for (int i = 0; i < 4; ++i) acc[mt][nt][i] = 0.f;

        mma_pass(smb + OFF_AGH, smb + OFF_AGL, smb + OFF_WLH,
                 acc, rowA256, rowA7, kbitA, rw256, rw7, kgrpW);
        mma_pass(smb + OFF_AXH, smb + OFF_AXL, smb + OFF_WRH,
                 acc, rowA256, rowA7, kbitA, rw256, rw7, kgrpW);

        // epilogue
        int row0 = tile * BM;
#pragma unroll
        for (int mt = 0; mt < 2; ++mt) {
#pragma unroll
            for (int half = 0; half < 2; ++half) {
                int row = row0 + warp_m * 32 + mt * 16 + g + half * 8;
                if (row < n) {
                    float* op = out + (size_t)row * CH + warp_n * 32 + c2;
#pragma unroll
                    for (int nt = 0; nt < 4; ++nt) {
                        int col = warp_n * 32 + nt * 8 + c2;
                        float2 v;
                        v.x = acc[mt][nt][half * 2 + 0] + sBias[col];
                        v.y = acc[mt][nt][half * 2 + 1] + sBias[col + 1];
                        if (apply_sig) {
                            v.x = 1.0f / (1.0f + __expf(-v.x));
                            v.y = 1.0f / (1.0f + __expf(-v.y));
                        }
                        *(float2*)(op + nt * 8) = v;
                    }
                }
            }
        }
    }
}

extern "C" void kernel_launch(void* const* d_in, const int* in_sizes, int n_in,
                              void* d_out, int out_size) {
    const float* x   = (const float*)d_in[0];
    const int*   ei  = (const int*)d_in[1];
    const float* W1l = (const float*)d_in[2];
    const float* b1l = (const float*)d_in[3];
    const float* W1r = (const float*)d_in[4];
    const float* W2l = (const float*)d_in[5];
    const float* b2l = (const float*)d_in[6];
    const float* W2r = (const float*)d_in[7];
    float* out = (float*)d_out;

    int n = in_sizes[0] / CH;   // 100000
    int E = in_sizes[1] / 2;    // 625000
    if (E > EMAX) E = EMAX;

    float* h_ptr = nullptr;
    cudaGetSymbolAddress((void**)&h_ptr, g_h);

    cudaFuncSetAttribute(layer_kernel,
                         cudaFuncAttributeMaxDynamicSharedMemorySize, SMEM_TOTAL);

    int ntiles = (n + BM - 1) / BM;
    int grid_layer = ntiles < 148 ? ntiles : 148;
    int grid_edge = (E + 255) / 256;
    int nblk = (n + 1023) / 1024;
    int grid_agg = (int)(((long long)n * 32 + 255) / 256);

    // CSR preprocessing (once; reused by both layers)
    zero_detect_kernel<<<(n + 255) / 256, 256>>>(ei, E, n);
    hist_kernel<<<grid_edge, 256>>>(ei, E);
    scan_a_kernel<<<nblk, 256>>>(n);
    scan_c_kernel<<<nblk, 256>>>(n);
    reorder_kernel<<<grid_edge, 256>>>(ei, E);

    // Layer 1
    agg_kernel<<<grid_agg, 256>>>(x, n);
    layer_kernel<<<grid_layer, 256, SMEM_TOTAL>>>(x, W1l, W1r, b1l, h_ptr, n, 1, ntiles);

    // Layer 2
    agg_kernel<<<grid_agg, 256>>>(h_ptr, n);
    layer_kernel<<<grid_layer, 256, SMEM_TOTAL>>>(h_ptr, W2l, W2r, b2l, out, n, 0, ntiles);
}

// round 8
// speedup vs baseline: 3.9745x; 1.1348x over previous
#include <cuda_runtime.h>
#include <cuda_fp16.h>

#define NN 100000
#define EMAX 700000
#define CH 128
#define BM 64

typedef unsigned long long ull;
typedef unsigned int u32;

// ---- smem byte offsets (layer kernel) ----
#define OFF_BIAS 0
#define OFF_WLH 512
#define OFF_WRH (OFF_WLH + 32768)
#define OFF_AGH (OFF_WRH + 32768)
#define OFF_AGL (OFF_AGH + 16384)
#define OFF_AXH (OFF_AGL + 16384)
#define SMEM_TOTAL (OFF_AXH + 16384)   // 115200 bytes

__device__ __align__(128) float g_agg[(size_t)NN * CH];
__device__ __align__(128) __half g_xh[(size_t)NN * CH];   // fp16 copy of x
__device__ __align__(128) __half g_hh[(size_t)NN * CH];   // fp16 hidden layer
__device__ int g_deg[NN];
__device__ int g_off[NN + 1];
__device__ int g_cursor[NN];
__device__ int g_bsum[128];
__device__ int g_ssrc[EMAX];
__device__ int g_is64;

// ---------------- helpers ----------------
__device__ __forceinline__ u32 smem_u32(const void* p) {
    u32 a;
    asm("{ .reg .u64 t; cvta.to.shared.u64 t, %1; cvt.u32.u64 %0, t; }"
        : "=r"(a) : "l"(p));
    return a;
}
__device__ __forceinline__ void ldsm4(u32* r, u32 addr) {
    asm volatile("ldmatrix.sync.aligned.m8n8.x4.shared.b16 {%0,%1,%2,%3}, [%4];"
                 : "=r"(r[0]), "=r"(r[1]), "=r"(r[2]), "=r"(r[3]) : "r"(addr));
}
__device__ __forceinline__ void mma16816(float* d, const u32* a, const u32* b) {
    asm volatile(
        "mma.sync.aligned.m16n8k16.row.col.f32.f16.f16.f32 "
        "{%0,%1,%2,%3}, {%4,%5,%6,%7}, {%8,%9}, {%0,%1,%2,%3};"
        : "+f"(d[0]), "+f"(d[1]), "+f"(d[2]), "+f"(d[3])
        : "r"(a[0]), "r"(a[1]), "r"(a[2]), "r"(a[3]), "r"(b[0]), "r"(b[1]));
}
__device__ __forceinline__ ull pack4h(__half a, __half b, __half c, __half d) {
    u32 lo = ((u32)__half_as_ushort(b) << 16) | __half_as_ushort(a);
    u32 hi = ((u32)__half_as_ushort(d) << 16) | __half_as_ushort(c);
    return ((ull)hi << 32) | lo;
}
// byte offset of 4 fp16 at (row r, group-of-4 q); 256B rows, 16B-chunk XOR swizzle.
__device__ __forceinline__ u32 swz_off(int r, int q) {
    return ((u32)r << 8) + ((u32)(((q >> 1) ^ (r & 7))) << 4) + ((u32)(q & 1) << 3);
}
// fp32 -> exact fp16 split (hi + residual lo).
__device__ __forceinline__ void split_store_a(char* hi, char* lo, int r, int q, float4 v) {
    __half hx = __float2half_rn(v.x);
    __half hy = __float2half_rn(v.y);
    __half hz = __float2half_rn(v.z);
    __half hw = __float2half_rn(v.w);
    u32 off = swz_off(r, q);
    *(ull*)(hi + off) = pack4h(hx, hy, hz, hw);
    *(ull*)(lo + off) = pack4h(
        __float2half_rn(v.x - __half2float(hx)),
        __float2half_rn(v.y - __half2float(hy)),
        __float2half_rn(v.z - __half2float(hz)),
        __float2half_rn(v.w - __half2float(hw)));
}
__device__ __forceinline__ void round_store_w(char* hi, int r, int q, float4 v) {
    *(ull*)(hi + swz_off(r, q)) = pack4h(
        __float2half_rn(v.x), __float2half_rn(v.y),
        __float2half_rn(v.z), __float2half_rn(v.w));
}

// ---------------- graph preprocessing (CSR by dst, once per replay) ----------------
__global__ void zero_detect_kernel(const int* __restrict__ ei, int E, int n) {
    int i = blockIdx.x * blockDim.x + threadIdx.x;
    if (i < n) g_deg[i] = 0;
    if (blockIdx.x == 0) {
        __shared__ int s_any;
        if (threadIdx.x == 0) s_any = 0;
        __syncthreads();
        int nchk = E < 1024 ? E : 1024;
        int acc = 0;
        for (int e = threadIdx.x; e < nchk; e += blockDim.x)
            acc |= ei[2 * e + 1];
        if (acc) atomicOr(&s_any, 1);
        __syncthreads();
        if (threadIdx.x == 0) g_is64 = (s_any ? 0 : 1);
    }
}

// histogram + (fused) x -> fp16 conversion
__global__ void hist_convert_kernel(const int* __restrict__ ei, int E,
                                    const float* __restrict__ x, int n) {
    int gid = blockIdx.x * blockDim.x + threadIdx.x;
    if (gid < E) {
        int dst = g_is64 ? ei[2 * (E + gid)] : ei[E + gid];
        atomicAdd(&g_deg[dst], 1);
    }
    int total4 = n * 32;
    int stride = gridDim.x * blockDim.x;
    uint2* xh2 = (uint2*)g_xh;
    for (int i = gid; i < total4; i += stride) {
        float4 v = ((const float4*)x)[i];
        __half2 a = __floats2half2_rn(v.x, v.y);
        __half2 b = __floats2half2_rn(v.z, v.w);
        uint2 u;
        u.x = *(u32*)&a;
        u.y = *(u32*)&b;
        xh2[i] = u;
    }
}

// scan stage A: per-block (1024 elems) sums
__global__ void scan_a_kernel(int n) {
    __shared__ int ssum[256];
    int tid = threadIdx.x;
    int base = blockIdx.x * 1024 + tid * 4;
    int s = 0;
#pragma unroll
    for (int j = 0; j < 4; ++j) {
        int i = base + j;
        if (i < n) s += g_deg[i];
    }
    ssum[tid] = s;
    __syncthreads();
    for (int off = 128; off > 0; off >>= 1) {
        if (tid < off) ssum[tid] += ssum[tid + off];
        __syncthreads();
    }
    if (tid == 0) g_bsum[blockIdx.x] = ssum[0];
}

// scan stage C: block-sum prefix + per-block exclusive scan; writes g_off/g_cursor.
__global__ void scan_c_kernel(int n) {
    __shared__ int sdata[256];
    __shared__ int s_boff;
    int tid = threadIdx.x;

    int partial = 0;
    for (int b = tid; b < (int)blockIdx.x; b += 256) partial += g_bsum[b];
    sdata[tid] = partial;
    __syncthreads();
    for (int off = 128; off > 0; off >>= 1) {
        if (tid < off) sdata[tid] += sdata[tid + off];
        __syncthreads();
    }
    if (tid == 0) s_boff = sdata[0];
    __syncthreads();

    int base = blockIdx.x * 1024 + tid * 4;
    int v[4];
    int tsum = 0;
#pragma unroll
    for (int j = 0; j < 4; ++j) {
        int i = base + j;
        v[j] = (i < n) ? g_deg[i] : 0;
        tsum += v[j];
    }
    sdata[tid] = tsum;
    __syncthreads();
    for (int off = 1; off < 256; off <<= 1) {
        int t = (tid >= off) ? sdata[tid - off] : 0;
        __syncthreads();
        sdata[tid] += t;
        __syncthreads();
    }
    int excl = sdata[tid] - tsum + s_boff;
#pragma unroll
    for (int j = 0; j < 4; ++j) {
        int i = base + j;
        if (i < n) {
            g_off[i] = excl;
            g_cursor[i] = excl;
            excl += v[j];
        }
    }
    if (blockIdx.x == gridDim.x - 1 && tid == 255)
        g_off[n] = s_boff + sdata[255];
}

__global__ void reorder_kernel(const int* __restrict__ ei, int E) {
    int e = blockIdx.x * blockDim.x + threadIdx.x;
    if (e >= E) return;
    int src, dst;
    if (g_is64) {
        src = ei[2 * e];
        dst = ei[2 * (E + e)];
    } else {
        src = ei[e];
        dst = ei[E + e];
    }
    int pos = atomicAdd(&g_cursor[dst], 1);
    g_ssrc[pos] = src;
}

// ---------------- mean aggregation: one warp per dst, fp16 gather ----------------
__global__ void agg_kernel(const __half* __restrict__ feat, int n) {
    int gid = blockIdx.x * blockDim.x + threadIdx.x;
    int d = gid >> 5, lane = gid & 31;
    if (d >= n) return;
    int s = g_off[d], e = g_off[d + 1];
    const uint2* f2 = (const uint2*)feat;
    float4 acc = make_float4(0.f, 0.f, 0.f, 0.f);
    int i = s;
    for (; i + 3 < e; i += 4) {
        int s0 = g_ssrc[i], s1 = g_ssrc[i + 1], s2 = g_ssrc[i + 2], s3 = g_ssrc[i + 3];
        uint2 u0 = f2[(size_t)s0 * 32 + lane];
        uint2 u1 = f2[(size_t)s1 * 32 + lane];
        uint2 u2 = f2[(size_t)s2 * 32 + lane];
        uint2 u3 = f2[(size_t)s3 * 32 + lane];
#pragma unroll
        for (int t = 0; t < 4; ++t) {
            uint2 u = t == 0 ? u0 : t == 1 ? u1 : t == 2 ? u2 : u3;
            float2 a = __half22float2(*(__half2*)&u.x);
            float2 b = __half22float2(*(__half2*)&u.y);
            acc.x += a.x; acc.y += a.y; acc.z += b.x; acc.w += b.y;
        }
    }
    for (; i < e; ++i) {
        uint2 u = f2[(size_t)g_ssrc[i] * 32 + lane];
        float2 a = __half22float2(*(__half2*)&u.x);
        float2 b = __half22float2(*(__half2*)&u.y);
        acc.x += a.x; acc.y += a.y; acc.z += b.x; acc.w += b.y;
    }
    float inv = (e > s) ? 1.0f / (float)(e - s) : 0.0f;
    acc.x *= inv; acc.y *= inv; acc.z *= inv; acc.w *= inv;
    ((float4*)g_agg)[(size_t)d * 32 + lane] = acc;   // mean pre-folded, fp32
}

// ---------------- HMMA fused SAGE layer ----------------
// out = act( g_agg(mean) @ Wl^T + bl + A2h @ Wr^T )
// agg pass: exact 2-term fp16 split; root pass: A already fp16 -> 1 term.
__device__ __forceinline__ void mma_pass2(u32 abh, u32 abl, u32 wbh,
                                          float acc[2][4][4],
                                          const u32* rowA256, u32 rowA7, u32 kbitA,
                                          const u32* rw256, const u32* rw7, u32 kgrpW) {
#pragma unroll
    for (int ks = 0; ks < 8; ++ks) {
        u32 ks2 = (u32)(ks << 1);
        u32 ah[2][4], al[2][4], wh[2][4];
        u32 ca = ((ks2 | kbitA) ^ rowA7) << 4;
#pragma unroll
        for (int mt = 0; mt < 2; ++mt) {
            ldsm4(ah[mt], abh + rowA256[mt] + ca);
            ldsm4(al[mt], abl + rowA256[mt] + ca);
        }
#pragma unroll
        for (int nt2 = 0; nt2 < 2; ++nt2) {
            u32 cw = ((ks2 | kgrpW) ^ rw7[nt2]) << 4;
            ldsm4(wh[nt2], wbh + rw256[nt2] + cw);
        }
#pragma unroll
        for (int mt = 0; mt < 2; ++mt) {
#pragma unroll
            for (int nt = 0; nt < 4; ++nt) {
                const u32* bh = &wh[nt >> 1][(nt & 1) * 2];
                mma16816(acc[mt][nt], ah[mt], bh);
                mma16816(acc[mt][nt], al[mt], bh);
            }
        }
    }
}
__device__ __forceinline__ void mma_pass1(u32 abh, u32 wbh,
                                          float acc[2][4][4],
                                          const u32* rowA256, u32 rowA7, u32 kbitA,
                                          const u32* rw256, const u32* rw7, u32 kgrpW) {
#pragma unroll
    for (int ks = 0; ks < 8; ++ks) {
        u32 ks2 = (u32)(ks << 1);
        u32 ah[2][4], wh[2][4];
        u32 ca = ((ks2 | kbitA) ^ rowA7) << 4;
#pragma unroll
        for (int mt = 0; mt < 2; ++mt)
            ldsm4(ah[mt], abh + rowA256[mt] + ca);
#pragma unroll
        for (int nt2 = 0; nt2 < 2; ++nt2) {
            u32 cw = ((ks2 | kgrpW) ^ rw7[nt2]) << 4;
            ldsm4(wh[nt2], wbh + rw256[nt2] + cw);
        }
#pragma unroll
        for (int mt = 0; mt < 2; ++mt)
#pragma unroll
            for (int nt = 0; nt < 4; ++nt)
                mma16816(acc[mt][nt], ah[mt], &wh[nt >> 1][(nt & 1) * 2]);
    }
}

__global__ void __launch_bounds__(256, 1)
layer_kernel(const __half* __restrict__ A2h,
             const float* __restrict__ Wl,
             const float* __restrict__ Wr,
             const float* __restrict__ bl,
             float* __restrict__ outf,
             __half* __restrict__ outh,
             int n, int apply_sig, int ntiles) {
    extern __shared__ char sm[];
    u32 smb = smem_u32(sm);
    float* sBias = (float*)(sm + OFF_BIAS);
    int tid = threadIdx.x, wid = tid >> 5, lane = tid & 31;
    int warp_m = wid & 1, warp_n = wid >> 1;

    // Round both weight matrices ([n][k], 128x128) to fp16.
    for (int idx = tid; idx < 128 * 32; idx += 256) {
        int r = idx >> 5, q = idx & 31;
        round_store_w(sm + OFF_WLH, r, q, ((const float4*)Wl)[idx]);
        round_store_w(sm + OFF_WRH, r, q, ((const float4*)Wr)[idx]);
    }
    if (tid < 128) sBias[tid] = bl[tid];

    // ldmatrix address precomputation.
    u32 rowA256[2], rowA7;
    {
        int ra0 = warp_m * 32 + (lane & 15);
        rowA256[0] = (u32)(ra0 << 8);
        rowA256[1] = (u32)((ra0 + 16) << 8);
        rowA7 = (u32)(ra0 & 7);
    }
    u32 kbitA = (u32)(lane >> 4);
    u32 rw256[2], rw7[2];
    u32 kgrpW = (u32)((lane >> 3) & 1);
    {
        int base = warp_n * 32 + (lane & 7) + ((lane >> 4) << 3);
#pragma unroll
        for (int nt2 = 0; nt2 < 2; ++nt2) {
            int rw = base + nt2 * 16;
            rw256[nt2] = (u32)(rw << 8);
            rw7[nt2] = (u32)(rw & 7);
        }
    }
    int g = lane >> 2, c2 = (lane & 3) * 2;

    const float4* agg4 = (const float4*)g_agg;
    const uint2* x2 = (const uint2*)A2h;
    const float4 fz = make_float4(0.f, 0.f, 0.f, 0.f);

    float4 va[8];
    uint2 vx[8];
    int tile = blockIdx.x;

    if (tile < ntiles) {
        int row0 = tile * BM;
#pragma unroll
        for (int j = 0; j < 8; ++j) {
            int idx = tid + j * 256;
            int row = row0 + (idx >> 5);
            va[j] = (row < n) ? agg4[(size_t)row * 32 + (idx & 31)] : fz;
            vx[j] = (row < n) ? x2[(size_t)row * 32 + (idx & 31)] : make_uint2(0u, 0u);
        }
    }

    for (; tile < ntiles; tile += gridDim.x) {
        __syncthreads();   // prior tile MMA done reading A buffers (covers W on 1st)
#pragma unroll
        for (int j = 0; j < 8; ++j) {
            int idx = tid + j * 256;
            int r = idx >> 5, q = idx & 31;
            split_store_a(sm + OFF_AGH, sm + OFF_AGL, r, q, va[j]);
            *(uint2*)(sm + OFF_AXH + swz_off(r, q)) = vx[j];
        }
        __syncthreads();

        // Prefetch next tile's A registers; LDG latency hides under MMA below.
        int next = tile + gridDim.x;
        if (next < ntiles) {
            int row0 = next * BM;
#pragma unroll
            for (int j = 0; j < 8; ++j) {
                int idx = tid + j * 256;
                int row = row0 + (idx >> 5);
                va[j] = (row < n) ? agg4[(size_t)row * 32 + (idx & 31)] : fz;
                vx[j] = (row < n) ? x2[(size_t)row * 32 + (idx & 31)] : make_uint2(0u, 0u);
            }
        }

        float acc[2][4][4];
#pragma unroll
        for (int mt = 0; mt < 2; ++mt)
#pragma unroll
            for (int nt = 0; nt < 4; ++nt)
#pragma unroll
                for (int i = 0; i < 4; ++i) acc[mt][nt][i] = 0.f;

        mma_pass2(smb + OFF_AGH, smb + OFF_AGL, smb + OFF_WLH,
                  acc, rowA256, rowA7, kbitA, rw256, rw7, kgrpW);
        mma_pass1(smb + OFF_AXH, smb + OFF_WRH,
                  acc, rowA256, rowA7, kbitA, rw256, rw7, kgrpW);

        // epilogue
        int row0 = tile * BM;
#pragma unroll
        for (int mt = 0; mt < 2; ++mt) {
#pragma unroll
            for (int half = 0; half < 2; ++half) {
                int row = row0 + warp_m * 32 + mt * 16 + g + half * 8;
                if (row < n) {
#pragma unroll
                    for (int nt = 0; nt < 4; ++nt) {
                        int col = warp_n * 32 + nt * 8 + c2;
                        float2 v;
                        v.x = acc[mt][nt][half * 2 + 0] + sBias[col];
                        v.y = acc[mt][nt][half * 2 + 1] + sBias[col + 1];
                        if (apply_sig) {
                            v.x = 1.0f / (1.0f + __expf(-v.x));
                            v.y = 1.0f / (1.0f + __expf(-v.y));
                            __half2 hv = __floats2half2_rn(v.x, v.y);
                            *(__half2*)(outh + (size_t)row * CH + col) = hv;
                        } else {
                            *(float2*)(outf + (size_t)row * CH + col) = v;
                        }
                    }
                }
            }
        }
    }
}

extern "C" void kernel_launch(void* const* d_in, const int* in_sizes, int n_in,
                              void* d_out, int out_size) {
    const float* x   = (const float*)d_in[0];
    const int*   ei  = (const int*)d_in[1];
    const float* W1l = (const float*)d_in[2];
    const float* b1l = (const float*)d_in[3];
    const float* W1r = (const float*)d_in[4];
    const float* W2l = (const float*)d_in[5];
    const float* b2l = (const float*)d_in[6];
    const float* W2r = (const float*)d_in[7];
    float* out = (float*)d_out;

    int n = in_sizes[0] / CH;   // 100000
    int E = in_sizes[1] / 2;    // 625000
    if (E > EMAX) E = EMAX;

    __half* xh_ptr = nullptr;
    __half* hh_ptr = nullptr;
    cudaGetSymbolAddress((void**)&xh_ptr, g_xh);
    cudaGetSymbolAddress((void**)&hh_ptr, g_hh);

    cudaFuncSetAttribute(layer_kernel,
                         cudaFuncAttributeMaxDynamicSharedMemorySize, SMEM_TOTAL);

    int ntiles = (n + BM - 1) / BM;
    int grid_layer = ntiles < 148 ? ntiles : 148;
    int grid_edge = (E + 255) / 256;
    int nblk = (n + 1023) / 1024;
    int grid_agg = (int)(((long long)n * 32 + 255) / 256);

    // CSR preprocessing + x->fp16 (once; reused by both layers)
    zero_detect_kernel<<<(n + 255) / 256, 256>>>(ei, E, n);
    hist_convert_kernel<<<grid_edge, 256>>>(ei, E, x, n);
    scan_a_kernel<<<nblk, 256>>>(n);
    scan_c_kernel<<<nblk, 256>>>(n);
    reorder_kernel<<<grid_edge, 256>>>(ei, E);

    // Layer 1
    agg_kernel<<<grid_agg, 256>>>(xh_ptr, n);
    layer_kernel<<<grid_layer, 256, SMEM_TOTAL>>>(xh_ptr, W1l, W1r, b1l,
                                                  nullptr, hh_ptr, n, 1, ntiles);

    // Layer 2
    agg_kernel<<<grid_agg, 256>>>(hh_ptr, n);
    layer_kernel<<<grid_layer, 256, SMEM_TOTAL>>>(hh_ptr, W2l, W2r, b2l,
                                                  out, nullptr, n, 0, ntiles);
}

// round 9
// speedup vs baseline: 4.4680x; 1.1242x over previous
#include <cuda_runtime.h>
#include <cuda_fp16.h>

#define NN 100000
#define EMAX 700000
#define CH 128
#define BM 64

typedef unsigned long long ull;
typedef unsigned int u32;

// ---- smem byte offsets (layer kernel) ----
#define OFF_BIAS 0
#define OFF_WLH 512
#define OFF_WRH (OFF_WLH + 32768)
#define OFF_AGH (OFF_WRH + 32768)
#define OFF_AXH (OFF_AGH + 16384)
#define SMEM_TOTAL (OFF_AXH + 16384)   // 98816 bytes

__device__ __align__(128) __half g_aggh[(size_t)NN * CH]; // fp16 mean-aggregated
__device__ __align__(128) __half g_xh[(size_t)NN * CH];   // fp16 copy of x
__device__ __align__(128) __half g_hh[(size_t)NN * CH];   // fp16 hidden layer
__device__ int g_deg[NN];
__device__ int g_off[NN + 1];
__device__ int g_cursor[NN];
__device__ int g_bsum[128];
__device__ int g_ssrc[EMAX];
__device__ int g_is64;

// ---------------- helpers ----------------
__device__ __forceinline__ u32 smem_u32(const void* p) {
    u32 a;
    asm("{ .reg .u64 t; cvta.to.shared.u64 t, %1; cvt.u32.u64 %0, t; }"
        : "=r"(a) : "l"(p));
    return a;
}
__device__ __forceinline__ void ldsm4(u32* r, u32 addr) {
    asm volatile("ldmatrix.sync.aligned.m8n8.x4.shared.b16 {%0,%1,%2,%3}, [%4];"
                 : "=r"(r[0]), "=r"(r[1]), "=r"(r[2]), "=r"(r[3]) : "r"(addr));
}
__device__ __forceinline__ void mma16816(float* d, const u32* a, const u32* b) {
    asm volatile(
        "mma.sync.aligned.m16n8k16.row.col.f32.f16.f16.f32 "
        "{%0,%1,%2,%3}, {%4,%5,%6,%7}, {%8,%9}, {%0,%1,%2,%3};"
        : "+f"(d[0]), "+f"(d[1]), "+f"(d[2]), "+f"(d[3])
        : "r"(a[0]), "r"(a[1]), "r"(a[2]), "r"(a[3]), "r"(b[0]), "r"(b[1]));
}
__device__ __forceinline__ ull pack4h(__half a, __half b, __half c, __half d) {
    u32 lo = ((u32)__half_as_ushort(b) << 16) | __half_as_ushort(a);
    u32 hi = ((u32)__half_as_ushort(d) << 16) | __half_as_ushort(c);
    return ((ull)hi << 32) | lo;
}
// byte offset of 4 fp16 at (row r, group-of-4 q); 256B rows, 16B-chunk XOR swizzle.
__device__ __forceinline__ u32 swz_off(int r, int q) {
    return ((u32)r << 8) + ((u32)(((q >> 1) ^ (r & 7))) << 4) + ((u32)(q & 1) << 3);
}
__device__ __forceinline__ void round_store_w(char* hi, int r, int q, float4 v) {
    *(ull*)(hi + swz_off(r, q)) = pack4h(
        __float2half_rn(v.x), __float2half_rn(v.y),
        __float2half_rn(v.z), __float2half_rn(v.w));
}

// ---------------- graph preprocessing (CSR by dst, once per replay) ----------------
__global__ void zero_detect_kernel(const int* __restrict__ ei, int E, int n) {
    int i = blockIdx.x * blockDim.x + threadIdx.x;
    if (i < n) g_deg[i] = 0;
    if (blockIdx.x == 0) {
        __shared__ int s_any;
        if (threadIdx.x == 0) s_any = 0;
        __syncthreads();
        int nchk = E < 1024 ? E : 1024;
        int acc = 0;
        for (int e = threadIdx.x; e < nchk; e += blockDim.x)
            acc |= ei[2 * e + 1];
        if (acc) atomicOr(&s_any, 1);
        __syncthreads();
        if (threadIdx.x == 0) g_is64 = (s_any ? 0 : 1);
    }
}

// histogram + (fused) x -> fp16 conversion
__global__ void hist_convert_kernel(const int* __restrict__ ei, int E,
                                    const float* __restrict__ x, int n) {
    int gid = blockIdx.x * blockDim.x + threadIdx.x;
    if (gid < E) {
        int dst = g_is64 ? ei[2 * (E + gid)] : ei[E + gid];
        atomicAdd(&g_deg[dst], 1);
    }
    int total4 = n * 32;
    int stride = gridDim.x * blockDim.x;
    uint2* xh2 = (uint2*)g_xh;
    for (int i = gid; i < total4; i += stride) {
        float4 v = ((const float4*)x)[i];
        __half2 a = __floats2half2_rn(v.x, v.y);
        __half2 b = __floats2half2_rn(v.z, v.w);
        uint2 u;
        u.x = *(u32*)&a;
        u.y = *(u32*)&b;
        xh2[i] = u;
    }
}

// scan stage A: per-block (1024 elems) sums
__global__ void scan_a_kernel(int n) {
    __shared__ int ssum[256];
    int tid = threadIdx.x;
    int base = blockIdx.x * 1024 + tid * 4;
    int s = 0;
#pragma unroll
    for (int j = 0; j < 4; ++j) {
        int i = base + j;
        if (i < n) s += g_deg[i];
    }
    ssum[tid] = s;
    __syncthreads();
    for (int off = 128; off > 0; off >>= 1) {
        if (tid < off) ssum[tid] += ssum[tid + off];
        __syncthreads();
    }
    if (tid == 0) g_bsum[blockIdx.x] = ssum[0];
}

// scan stage C: block-sum prefix + per-block exclusive scan; writes g_off/g_cursor.
__global__ void scan_c_kernel(int n) {
    __shared__ int sdata[256];
    __shared__ int s_boff;
    int tid = threadIdx.x;

    int partial = 0;
    for (int b = tid; b < (int)blockIdx.x; b += 256) partial += g_bsum[b];
    sdata[tid] = partial;
    __syncthreads();
    for (int off = 128; off > 0; off >>= 1) {
        if (tid < off) sdata[tid] += sdata[tid + off];
        __syncthreads();
    }
    if (tid == 0) s_boff = sdata[0];
    __syncthreads();

    int base = blockIdx.x * 1024 + tid * 4;
    int v[4];
    int tsum = 0;
#pragma unroll
    for (int j = 0; j < 4; ++j) {
        int i = base + j;
        v[j] = (i < n) ? g_deg[i] : 0;
        tsum += v[j];
    }
    sdata[tid] = tsum;
    __syncthreads();
    for (int off = 1; off < 256; off <<= 1) {
        int t = (tid >= off) ? sdata[tid - off] : 0;
        __syncthreads();
        sdata[tid] += t;
        __syncthreads();
    }
    int excl = sdata[tid] - tsum + s_boff;
#pragma unroll
    for (int j = 0; j < 4; ++j) {
        int i = base + j;
        if (i < n) {
            g_off[i] = excl;
            g_cursor[i] = excl;
            excl += v[j];
        }
    }
    if (blockIdx.x == gridDim.x - 1 && tid == 255)
        g_off[n] = s_boff + sdata[255];
}

__global__ void reorder_kernel(const int* __restrict__ ei, int E) {
    int e = blockIdx.x * blockDim.x + threadIdx.x;
    if (e >= E) return;
    int src, dst;
    if (g_is64) {
        src = ei[2 * e];
        dst = ei[2 * (E + e)];
    } else {
        src = ei[e];
        dst = ei[E + e];
    }
    int pos = atomicAdd(&g_cursor[dst], 1);
    g_ssrc[pos] = src;
}

// ---------------- mean aggregation: one warp per dst, fp16 in/out ----------------
__global__ void agg_kernel(const __half* __restrict__ feat, int n) {
    int gid = blockIdx.x * blockDim.x + threadIdx.x;
    int d = gid >> 5, lane = gid & 31;
    if (d >= n) return;
    int s = g_off[d], e = g_off[d + 1];
    const uint2* f2 = (const uint2*)feat;
    float4 acc = make_float4(0.f, 0.f, 0.f, 0.f);
    int i = s;
    for (; i + 3 < e; i += 4) {
        int s0 = g_ssrc[i], s1 = g_ssrc[i + 1], s2 = g_ssrc[i + 2], s3 = g_ssrc[i + 3];
        uint2 u0 = f2[(size_t)s0 * 32 + lane];
        uint2 u1 = f2[(size_t)s1 * 32 + lane];
        uint2 u2 = f2[(size_t)s2 * 32 + lane];
        uint2 u3 = f2[(size_t)s3 * 32 + lane];
#pragma unroll
        for (int t = 0; t < 4; ++t) {
            uint2 u = t == 0 ? u0 : t == 1 ? u1 : t == 2 ? u2 : u3;
            float2 a = __half22float2(*(__half2*)&u.x);
            float2 b = __half22float2(*(__half2*)&u.y);
            acc.x += a.x; acc.y += a.y; acc.z += b.x; acc.w += b.y;
        }
    }
    for (; i < e; ++i) {
        uint2 u = f2[(size_t)g_ssrc[i] * 32 + lane];
        float2 a = __half22float2(*(__half2*)&u.x);
        float2 b = __half22float2(*(__half2*)&u.y);
        acc.x += a.x; acc.y += a.y; acc.z += b.x; acc.w += b.y;
    }
    float inv = (e > s) ? 1.0f / (float)(e - s) : 0.0f;
    __half2 h0 = __floats2half2_rn(acc.x * inv, acc.y * inv);
    __half2 h1 = __floats2half2_rn(acc.z * inv, acc.w * inv);
    uint2 u;
    u.x = *(u32*)&h0;
    u.y = *(u32*)&h1;
    ((uint2*)g_aggh)[(size_t)d * 32 + lane] = u;   // mean pre-folded, fp16
}

// ---------------- HMMA fused SAGE layer (all-fp16, 1 term per pass) ----------------
// out = act( aggh @ Wl^T + bl + A2h @ Wr^T )
__device__ __forceinline__ void mma_pass1(u32 abh, u32 wbh,
                                          float acc[2][4][4],
                                          const u32* rowA256, u32 rowA7, u32 kbitA,
                                          const u32* rw256, const u32* rw7, u32 kgrpW) {
#pragma unroll
    for (int ks = 0; ks < 8; ++ks) {
        u32 ks2 = (u32)(ks << 1);
        u32 ah[2][4], wh[2][4];
        u32 ca = ((ks2 | kbitA) ^ rowA7) << 4;
#pragma unroll
        for (int mt = 0; mt < 2; ++mt)
            ldsm4(ah[mt], abh + rowA256[mt] + ca);
#pragma unroll
        for (int nt2 = 0; nt2 < 2; ++nt2) {
            u32 cw = ((ks2 | kgrpW) ^ rw7[nt2]) << 4;
            ldsm4(wh[nt2], wbh + rw256[nt2] + cw);
        }
#pragma unroll
        for (int mt = 0; mt < 2; ++mt)
#pragma unroll
            for (int nt = 0; nt < 4; ++nt)
                mma16816(acc[mt][nt], ah[mt], &wh[nt >> 1][(nt & 1) * 2]);
    }
}

__global__ void __launch_bounds__(256, 1)
layer_kernel(const __half* __restrict__ A2h,
             const float* __restrict__ Wl,
             const float* __restrict__ Wr,
             const float* __restrict__ bl,
             float* __restrict__ outf,
             __half* __restrict__ outh,
             int n, int apply_sig, int ntiles) {
    extern __shared__ char sm[];
    u32 smb = smem_u32(sm);
    float* sBias = (float*)(sm + OFF_BIAS);
    int tid = threadIdx.x, wid = tid >> 5, lane = tid & 31;
    int warp_m = wid & 1, warp_n = wid >> 1;

    // Round both weight matrices ([n][k], 128x128) to fp16.
    for (int idx = tid; idx < 128 * 32; idx += 256) {
        int r = idx >> 5, q = idx & 31;
        round_store_w(sm + OFF_WLH, r, q, ((const float4*)Wl)[idx]);
        round_store_w(sm + OFF_WRH, r, q, ((const float4*)Wr)[idx]);
    }
    if (tid < 128) sBias[tid] = bl[tid];

    // ldmatrix address precomputation.
    u32 rowA256[2], rowA7;
    {
        int ra0 = warp_m * 32 + (lane & 15);
        rowA256[0] = (u32)(ra0 << 8);
        rowA256[1] = (u32)((ra0 + 16) << 8);
        rowA7 = (u32)(ra0 & 7);
    }
    u32 kbitA = (u32)(lane >> 4);
    u32 rw256[2], rw7[2];
    u32 kgrpW = (u32)((lane >> 3) & 1);
    {
        int base = warp_n * 32 + (lane & 7) + ((lane >> 4) << 3);
#pragma unroll
        for (int nt2 = 0; nt2 < 2; ++nt2) {
            int rw = base + nt2 * 16;
            rw256[nt2] = (u32)(rw << 8);
            rw7[nt2] = (u32)(rw & 7);
        }
    }
    int g = lane >> 2, c2 = (lane & 3) * 2;

    const uint2* ag2 = (const uint2*)g_aggh;
    const uint2* x2 = (const uint2*)A2h;
    const uint2 uz = make_uint2(0u, 0u);

    uint2 va[8], vx[8];
    int tile = blockIdx.x;

    if (tile < ntiles) {
        int row0 = tile * BM;
#pragma unroll
        for (int j = 0; j < 8; ++j) {
            int idx = tid + j * 256;
            int row = row0 + (idx >> 5);
            va[j] = (row < n) ? ag2[(size_t)row * 32 + (idx & 31)] : uz;
            vx[j] = (row < n) ? x2[(size_t)row * 32 + (idx & 31)] : uz;
        }
    }

    for (; tile < ntiles; tile += gridDim.x) {
        __syncthreads();   // prior tile MMA done reading A buffers (covers W on 1st)
#pragma unroll
        for (int j = 0; j < 8; ++j) {
            int idx = tid + j * 256;
            int r = idx >> 5, q = idx & 31;
            u32 off = swz_off(r, q);
            *(uint2*)(sm + OFF_AGH + off) = va[j];
            *(uint2*)(sm + OFF_AXH + off) = vx[j];
        }
        __syncthreads();

        // Prefetch next tile's A registers; LDG latency hides under MMA below.
        int next = tile + gridDim.x;
        if (next < ntiles) {
            int row0 = next * BM;
#pragma unroll
            for (int j = 0; j < 8; ++j) {
                int idx = tid + j * 256;
                int row = row0 + (idx >> 5);
                va[j] = (row < n) ? ag2[(size_t)row * 32 + (idx & 31)] : uz;
                vx[j] = (row < n) ? x2[(size_t)row * 32 + (idx & 31)] : uz;
            }
        }

        float acc[2][4][4];
#pragma unroll
        for (int mt = 0; mt < 2; ++mt)
#pragma unroll
            for (int nt = 0; nt < 4; ++nt)
#pragma unroll
                for (int i = 0; i < 4; ++i) acc[mt][nt][i] = 0.f;

        mma_pass1(smb + OFF_AGH, smb + OFF_WLH,
                  acc, rowA256, rowA7, kbitA, rw256, rw7, kgrpW);
        mma_pass1(smb + OFF_AXH, smb + OFF_WRH,
                  acc, rowA256, rowA7, kbitA, rw256, rw7, kgrpW);

        // epilogue
        int row0 = tile * BM;
#pragma unroll
        for (int mt = 0; mt < 2; ++mt) {
#pragma unroll
            for (int half = 0; half < 2; ++half) {
                int row = row0 + warp_m * 32 + mt * 16 + g + half * 8;
                if (row < n) {
#pragma unroll
                    for (int nt = 0; nt < 4; ++nt) {
                        int col = warp_n * 32 + nt * 8 + c2;
                        float2 v;
                        v.x = acc[mt][nt][half * 2 + 0] + sBias[col];
                        v.y = acc[mt][nt][half * 2 + 1] + sBias[col + 1];
                        if (apply_sig) {
                            v.x = 1.0f / (1.0f + __expf(-v.x));
                            v.y = 1.0f / (1.0f + __expf(-v.y));
                            __half2 hv = __floats2half2_rn(v.x, v.y);
                            *(__half2*)(outh + (size_t)row * CH + col) = hv;
                        } else {
                            *(float2*)(outf + (size_t)row * CH + col) = v;
                        }
                    }
                }
            }
        }
    }
}

extern "C" void kernel_launch(void* const* d_in, const int* in_sizes, int n_in,
                              void* d_out, int out_size) {
    const float* x   = (const float*)d_in[0];
    const int*   ei  = (const int*)d_in[1];
    const float* W1l = (const float*)d_in[2];
    const float* b1l = (const float*)d_in[3];
    const float* W1r = (const float*)d_in[4];
    const float* W2l = (const float*)d_in[5];
    const float* b2l = (const float*)d_in[6];
    const float* W2r = (const float*)d_in[7];
    float* out = (float*)d_out;

    int n = in_sizes[0] / CH;   // 100000
    int E = in_sizes[1] / 2;    // 625000
    if (E > EMAX) E = EMAX;

    __half* xh_ptr = nullptr;
    __half* hh_ptr = nullptr;
    cudaGetSymbolAddress((void**)&xh_ptr, g_xh);
    cudaGetSymbolAddress((void**)&hh_ptr, g_hh);

    cudaFuncSetAttribute(layer_kernel,
                         cudaFuncAttributeMaxDynamicSharedMemorySize, SMEM_TOTAL);

    int ntiles = (n + BM - 1) / BM;
    int grid_layer = ntiles < 148 ? ntiles : 148;
    int grid_edge = (E + 255) / 256;
    int nblk = (n + 1023) / 1024;
    int grid_agg = (int)(((long long)n * 32 + 255) / 256);

    // CSR preprocessing + x->fp16 (once; reused by both layers)
    zero_detect_kernel<<<(n + 255) / 256, 256>>>(ei, E, n);
    hist_convert_kernel<<<grid_edge, 256>>>(ei, E, x, n);
    scan_a_kernel<<<nblk, 256>>>(n);
    scan_c_kernel<<<nblk, 256>>>(n);
    reorder_kernel<<<grid_edge, 256>>>(ei, E);

    // Layer 1
    agg_kernel<<<grid_agg, 256>>>(xh_ptr, n);
    layer_kernel<<<grid_layer, 256, SMEM_TOTAL>>>(xh_ptr, W1l, W1r, b1l,
                                                  nullptr, hh_ptr, n, 1, ntiles);

    // Layer 2
    agg_kernel<<<grid_agg, 256>>>(hh_ptr, n);
    layer_kernel<<<grid_layer, 256, SMEM_TOTAL>>>(hh_ptr, W2l, W2r, b2l,
                                                  out, nullptr, n, 0, ntiles);
}